// round 12
// baseline (speedup 1.0000x reference)
#include <cuda_runtime.h>
#include <cuda_fp16.h>

#define Bq 512
#define Tq 128
#define Eq 256
#define Dq 256
#define G4 1024
#define BT (Bq*Tq)
#define NBLK 512
#define NLEAF 16
#define PER_LEAF 32   // 512 = 16*32

// ---------------- static device scratch ----------------
__device__ __half g_pre[(size_t)BT * Eq];     // enc @ W1_enc + b1 (fp16, 32MB)
__device__ float g_encfc[BT];                 // enc[b,t,:] . fc_w[0:256]
__device__ float g_whhT[Dq * G4];             // w_hh transposed [k][gate*256+d]
__device__ float g_bsum[G4];
__device__ float g_h[Bq * Dq];
__device__ float g_c[Bq * Dq];
__device__ float g_hp[16 * Bq * Eq];          // 16 K-partials of [h|c]@W1_hc
__device__ float g_gp[4 * (size_t)Bq * G4];   // 4 K-partials of h@w_hhT
__device__ unsigned g_cnt[NLEAF * 32];
__device__ unsigned g_master;
__device__ volatile unsigned g_gen;

// double-buffered GEMM smem: A fp32 (140-pad: 2-way store conflict only),
// B pre-duplicated as (b,b) float2 pairs for packless FFMA2.
struct SmA2 { float As[2][16][140]; float2 Bsd[2][16][64]; };
struct SmB {
    float hp[256]; unsigned hp2[128]; float sc[128]; float ctxp[8][256];
    float ctx[256]; float red[8]; float misc[4];
};
struct SmAll { union { SmA2 a; SmB b; } u; float w2s[256]; };

__device__ __forceinline__ unsigned tanh_h2(unsigned x) {
    unsigned y; asm("tanh.approx.f16x2 %0, %1;" : "=r"(y) : "r"(x)); return y;
}
__device__ __forceinline__ float sigmoid_f(float x) {
    return __fdividef(1.0f, 1.0f + __expf(-x));
}

// packed dual-fp32 FMA
#define FMA_X2(acc, a, b) \
    asm("fma.rn.f32x2 %0, %1, %2, %0;" : "+l"(acc) : "l"(a), "l"(b))

__device__ __forceinline__ float2 unpack2(unsigned long long v) {
    float lo, hi;
    asm("mov.b64 {%0, %1}, %2;" : "=f"(lo), "=f"(hi) : "l"(v));
    return make_float2(lo, hi);
}

__device__ __forceinline__ void stage_store(SmA2* s, int buf,
        int arow, int ac4, int bk, int bc4,
        float4 av0, float4 av1, float4 bv)
{
    s->As[buf][ac4 + 0][arow] = av0.x; s->As[buf][ac4 + 1][arow] = av0.y;
    s->As[buf][ac4 + 2][arow] = av0.z; s->As[buf][ac4 + 3][arow] = av0.w;
    s->As[buf][ac4 + 0][arow + 64] = av1.x; s->As[buf][ac4 + 1][arow + 64] = av1.y;
    s->As[buf][ac4 + 2][arow + 64] = av1.z; s->As[buf][ac4 + 3][arow + 64] = av1.w;
    float2* bd = &s->Bsd[buf][bk][bc4];
    bd[0] = make_float2(bv.x, bv.x);
    bd[1] = make_float2(bv.y, bv.y);
    bd[2] = make_float2(bv.z, bv.z);
    bd[3] = make_float2(bv.w, bv.w);
}

// 128x64 output tile, K multiple of 16, 256 threads, 8x4 microtile.
// Double-buffered, packless FFMA2 inner loop, one sync per k-slab.
template<typename TO>
__device__ __forceinline__ void gemm128x64(SmA2* s,
        const float* __restrict__ A, int lda,
        const float* __restrict__ Bm, int ldb,
        TO* __restrict__ C, int ldc, int K,
        const float* __restrict__ bias)
{
    const int tid = threadIdx.x;
    const int ty = tid >> 4, tx = tid & 15;
    const int arow = tid >> 2, ac4 = (tid & 3) << 2;
    const int bk = tid >> 4, bc4 = (tid & 15) << 2;

    unsigned long long acc2[4][4];
#pragma unroll
    for (int p = 0; p < 4; p++)
#pragma unroll
        for (int j = 0; j < 4; j++) acc2[p][j] = 0ull;

    float4 av0 = __ldcg((const float4*)(A + (size_t)arow * lda + ac4));
    float4 av1 = __ldcg((const float4*)(A + (size_t)(arow + 64) * lda + ac4));
    float4 bv  = __ldg((const float4*)(Bm + (size_t)bk * ldb + bc4));
    stage_store(s, 0, arow, ac4, bk, bc4, av0, av1, bv);
    __syncthreads();

    int cur = 0;
    for (int k0 = 0; k0 < K; k0 += 16) {
        bool more = (k0 + 16) < K;
        if (more) {
            av0 = __ldcg((const float4*)(A + (size_t)arow * lda + k0 + 16 + ac4));
            av1 = __ldcg((const float4*)(A + (size_t)(arow + 64) * lda + k0 + 16 + ac4));
            bv  = __ldg((const float4*)(Bm + (size_t)(k0 + 16 + bk) * ldb + bc4));
        }
#pragma unroll
        for (int k = 0; k < 16; k++) {
            ulonglong2 a01 = *(const ulonglong2*)&s->As[cur][k][ty << 3];
            ulonglong2 a23 = *(const ulonglong2*)&s->As[cur][k][(ty << 3) + 4];
            ulonglong2 b01 = *(const ulonglong2*)&s->Bsd[cur][k][tx << 2];
            ulonglong2 b23 = *(const ulonglong2*)&s->Bsd[cur][k][(tx << 2) + 2];
            FMA_X2(acc2[0][0], a01.x, b01.x); FMA_X2(acc2[0][1], a01.x, b01.y);
            FMA_X2(acc2[0][2], a01.x, b23.x); FMA_X2(acc2[0][3], a01.x, b23.y);
            FMA_X2(acc2[1][0], a01.y, b01.x); FMA_X2(acc2[1][1], a01.y, b01.y);
            FMA_X2(acc2[1][2], a01.y, b23.x); FMA_X2(acc2[1][3], a01.y, b23.y);
            FMA_X2(acc2[2][0], a23.x, b01.x); FMA_X2(acc2[2][1], a23.x, b01.y);
            FMA_X2(acc2[2][2], a23.x, b23.x); FMA_X2(acc2[2][3], a23.x, b23.y);
            FMA_X2(acc2[3][0], a23.y, b01.x); FMA_X2(acc2[3][1], a23.y, b01.y);
            FMA_X2(acc2[3][2], a23.y, b23.x); FMA_X2(acc2[3][3], a23.y, b23.y);
        }
        if (more) {
            stage_store(s, cur ^ 1, arow, ac4, bk, bc4, av0, av1, bv);
            __syncthreads();
            cur ^= 1;
        }
    }

#pragma unroll
    for (int p = 0; p < 4; p++) {
        float2 v0 = unpack2(acc2[p][0]);
        float2 v1 = unpack2(acc2[p][1]);
        float2 v2 = unpack2(acc2[p][2]);
        float2 v3 = unpack2(acc2[p][3]);
        float r0[4] = {v0.x, v1.x, v2.x, v3.x};
        float r1[4] = {v0.y, v1.y, v2.y, v3.y};
        if (bias) {
#pragma unroll
            for (int j = 0; j < 4; j++) {
                float bj = bias[(tx << 2) + j];
                r0[j] += bj; r1[j] += bj;
            }
        }
        size_t off0 = (size_t)((ty << 3) + 2 * p) * ldc + (tx << 2);
        size_t off1 = off0 + ldc;
        if constexpr (sizeof(TO) == 2) {
            __half2 h00 = __floats2half2_rn(r0[0], r0[1]);
            __half2 h01 = __floats2half2_rn(r0[2], r0[3]);
            __half2 h10 = __floats2half2_rn(r1[0], r1[1]);
            __half2 h11 = __floats2half2_rn(r1[2], r1[3]);
            uint2 u0; u0.x = *(unsigned*)&h00; u0.y = *(unsigned*)&h01;
            uint2 u1; u1.x = *(unsigned*)&h10; u1.y = *(unsigned*)&h11;
            *(uint2*)((__half*)C + off0) = u0;
            *(uint2*)((__half*)C + off1) = u1;
        } else {
            *(float4*)((float*)C + off0) = make_float4(r0[0], r0[1], r0[2], r0[3]);
            *(float4*)((float*)C + off1) = make_float4(r1[0], r1[1], r1[2], r1[3]);
        }
    }
    __syncthreads();
}

// one uint4 (8 fp16 pre values) of the score dot-product, fp32 accumulate
__device__ __forceinline__ void score_u4(uint4 p, uint4 h,
        float4 wa, float4 wb, float& acc)
{
    const __half2* ph = (const __half2*)&p;
    const __half2* hh = (const __half2*)&h;
    __half2 x0 = __hadd2(ph[0], hh[0]);
    __half2 x1 = __hadd2(ph[1], hh[1]);
    __half2 x2 = __hadd2(ph[2], hh[2]);
    __half2 x3 = __hadd2(ph[3], hh[3]);
    unsigned t0 = tanh_h2(*(unsigned*)&x0);
    unsigned t1 = tanh_h2(*(unsigned*)&x1);
    unsigned t2 = tanh_h2(*(unsigned*)&x2);
    unsigned t3 = tanh_h2(*(unsigned*)&x3);
    float2 f0 = __half22float2(*(const __half2*)&t0);
    float2 f1 = __half22float2(*(const __half2*)&t1);
    float2 f2 = __half22float2(*(const __half2*)&t2);
    float2 f3 = __half22float2(*(const __half2*)&t3);
    acc = fmaf(wa.x, f0.x, acc); acc = fmaf(wa.y, f0.y, acc);
    acc = fmaf(wa.z, f1.x, acc); acc = fmaf(wa.w, f1.y, acc);
    acc = fmaf(wb.x, f2.x, acc); acc = fmaf(wb.y, f2.y, acc);
    acc = fmaf(wb.z, f3.x, acc); acc = fmaf(wb.w, f3.y, acc);
}

__device__ __forceinline__ void gridbar() {
    __threadfence();
    __syncthreads();
    if (threadIdx.x == 0) {
        unsigned gen = g_gen;
        unsigned leaf = (blockIdx.x & (NLEAF - 1)) * 32;
        unsigned v = atomicAdd(&g_cnt[leaf], 1u) + 1u;
        if (v == (gen + 1u) * PER_LEAF) {
            unsigned m = atomicAdd(&g_master, 1u) + 1u;
            if (m == (gen + 1u) * NLEAF) {
                __threadfence();
                g_gen = gen + 1u;
            } else {
                while (g_gen == gen) __nanosleep(32);
            }
        } else {
            while (g_gen == gen) __nanosleep(64);
        }
        __threadfence();
    }
    __syncthreads();
}

__global__ void __launch_bounds__(256, 4) decoder_persist(
        const float* __restrict__ enc, const float* __restrict__ yhist,
        const float* __restrict__ attn_w1, const float* __restrict__ attn_w2,
        const float* __restrict__ w_ih,
        const float* __restrict__ fc_w, const float* __restrict__ fc_b,
        const float* __restrict__ fcf_w, const float* __restrict__ fcf_b,
        float* __restrict__ out)
{
    __shared__ SmAll sm;
    const int bid = blockIdx.x;
    const int tid = threadIdx.x;
    const int lane = tid & 31, warp = tid >> 5;
    const int b = bid;

    sm.w2s[tid] = __ldg(&attn_w2[tid]);   // immutable; first gemm sync covers it

    for (int t = 0; t < Tq; t++) {
        // ============ phase 1: step-GEMM partials, one unit per block ============
        if (bid < 256) {
            int kq = bid & 3, tile = bid >> 2;
            int mt = tile >> 4, nt = tile & 15;
            gemm128x64<float>(&sm.u.a,
                g_h + (size_t)mt * 128 * Dq + kq * 64, Dq,
                g_whhT + (size_t)(kq * 64) * G4 + nt * 64, G4,
                g_gp + (size_t)kq * (Bq * G4) + (size_t)mt * 128 * G4 + nt * 64, G4,
                64, (const float*)0);
        } else {
            int u = bid - 256;
            int tile = u >> 4, kq = u & 15;
            int mt = tile >> 2, nt = tile & 3;
            const float* A = (kq < 8 ? g_h + kq * 32 : g_c + (kq - 8) * 32)
                             + (size_t)mt * 128 * Dq;
            gemm128x64<float>(&sm.u.a, A, Dq,
                attn_w1 + (size_t)(kq * 32) * Eq + nt * 64, Eq,
                g_hp + (size_t)kq * (Bq * Eq) + (size_t)mt * 128 * Eq + nt * 64, Eq,
                32, (const float*)0);
        }
        gridbar();

        // ============ phase 2: attention + LSTM, row-local (row b = bid) ============
        {
            float hpv = 0.f;
#pragma unroll
            for (int q = 0; q < 16; q++)
                hpv += __ldcg(&g_hp[(size_t)q * (Bq * Eq) + b * Eq + tid]);
            sm.u.b.hp[tid] = hpv;
            __syncthreads();
            if (tid < 128) {
                __half2 h2 = __floats2half2_rn(sm.u.b.hp[2 * tid], sm.u.b.hp[2 * tid + 1]);
                sm.u.b.hp2[tid] = *(unsigned*)&h2;
            }
            __syncthreads();

            // scores: one thread per (t, half); no shuffles
            {
                int ttt = tid & 127, hf = tid >> 7;
                const uint4* prow = (const uint4*)(g_pre + ((size_t)b * Tq + ttt) * Eq)
                                    + (hf << 4);
                float acc = 0.f;
#pragma unroll
                for (int i = 0; i < 4; i++) {
                    uint4 p0 = __ldg(prow + (i << 2) + 0);
                    uint4 p1 = __ldg(prow + (i << 2) + 1);
                    uint4 p2 = __ldg(prow + (i << 2) + 2);
                    uint4 p3 = __ldg(prow + (i << 2) + 3);
                    const uint4* hpq = (const uint4*)&sm.u.b.hp2[(hf << 6) + (i << 4)];
                    const float4* wq = (const float4*)&sm.w2s[(hf << 7) + (i << 5)];
                    score_u4(p0, hpq[0], wq[0], wq[1], acc);
                    score_u4(p1, hpq[1], wq[2], wq[3], acc);
                    score_u4(p2, hpq[2], wq[4], wq[5], acc);
                    score_u4(p3, hpq[3], wq[6], wq[7], acc);
                }
                sm.u.b.ctxp[hf][ttt] = acc;
            }
            __syncthreads();

            // softmax over T=128 (attn_b2 dropped: shift-invariant)
            float sv = (tid < Tq) ? sm.u.b.ctxp[0][tid] + sm.u.b.ctxp[1][tid] : -3.0e38f;
            float m = sv;
#pragma unroll
            for (int o = 16; o; o >>= 1) m = fmaxf(m, __shfl_xor_sync(0xffffffffu, m, o));
            if (lane == 0) sm.u.b.red[warp] = m;
            __syncthreads();
            if (tid == 0) {
                float mm = sm.u.b.red[0];
#pragma unroll
                for (int w = 1; w < 8; w++) mm = fmaxf(mm, sm.u.b.red[w]);
                sm.u.b.misc[0] = mm;
            }
            __syncthreads();
            float ex = (tid < Tq) ? __expf(sv - sm.u.b.misc[0]) : 0.f;
            float ss = ex;
#pragma unroll
            for (int o = 16; o; o >>= 1) ss += __shfl_xor_sync(0xffffffffu, ss, o);
            if (lane == 0) sm.u.b.red[warp] = ss;
            __syncthreads();
            if (tid == 0) {
                float tot = 0.f;
#pragma unroll
                for (int w = 0; w < 8; w++) tot += sm.u.b.red[w];
                sm.u.b.misc[1] = __fdividef(1.0f, tot);
            }
            if (tid < Tq) sm.u.b.sc[tid] = ex;
            __syncthreads();
            float invs = sm.u.b.misc[1];

            // y_dot = sum_t ex[t] * encfc[b,t]
            float yd = (tid < Tq) ? sm.u.b.sc[tid] * __ldg(&g_encfc[b * Tq + tid]) : 0.f;
#pragma unroll
            for (int o = 16; o; o >>= 1) yd += __shfl_xor_sync(0xffffffffu, yd, o);
            if (lane == 0) sm.u.b.red[warp] = yd;
            __syncthreads();
            if (tid == 0) {
                float tot = 0.f;
#pragma unroll
                for (int w = 0; w < 8; w++) tot += sm.u.b.red[w];
                sm.u.b.misc[2] = tot * invs + __ldg(&yhist[b * Tq + t]) * fc_w[256] + fc_b[0];
            }

            // full ctx only at the final step (for fc_final)
            if (t == Tq - 1) {
                float a8[8] = {0.f, 0.f, 0.f, 0.f, 0.f, 0.f, 0.f, 0.f};
                const float4* encb = (const float4*)(enc + (size_t)b * Tq * Eq);
#pragma unroll 2
                for (int i = 0; i < 16; i++) {
                    int tt = (warp << 4) + i;
                    float wgt = sm.u.b.sc[tt];
                    float4 e0 = __ldg(encb + (size_t)tt * 64 + lane * 2);
                    float4 e1 = __ldg(encb + (size_t)tt * 64 + lane * 2 + 1);
                    a8[0] = fmaf(wgt, e0.x, a8[0]); a8[1] = fmaf(wgt, e0.y, a8[1]);
                    a8[2] = fmaf(wgt, e0.z, a8[2]); a8[3] = fmaf(wgt, e0.w, a8[3]);
                    a8[4] = fmaf(wgt, e1.x, a8[4]); a8[5] = fmaf(wgt, e1.y, a8[5]);
                    a8[6] = fmaf(wgt, e1.z, a8[6]); a8[7] = fmaf(wgt, e1.w, a8[7]);
                }
                __syncthreads();
#pragma unroll
                for (int j = 0; j < 8; j++) sm.u.b.ctxp[warp][lane * 8 + j] = a8[j];
                __syncthreads();
                float cv = 0.f;
#pragma unroll
                for (int w = 0; w < 8; w++) cv += sm.u.b.ctxp[w][tid];
                sm.u.b.ctx[tid] = cv * invs;
            }
            __syncthreads();

            // LSTM epilogue (thread = d)
            float yt = sm.u.b.misc[2];
            int d = tid;
            float gv[4];
#pragma unroll
            for (int g = 0; g < 4; g++) {
                float a = fmaf(yt, __ldg(&w_ih[g * 256 + d]), g_bsum[g * 256 + d]);
#pragma unroll
                for (int kq = 0; kq < 4; kq++)
                    a += __ldcg(&g_gp[(size_t)kq * (Bq * G4) + (size_t)b * G4 + g * 256 + d]);
                gv[g] = a;
            }
            float cprev = __ldcg(&g_c[b * Dq + d]);
            float cn = sigmoid_f(gv[1]) * cprev + sigmoid_f(gv[0]) * tanhf(gv[2]);
            float hn = sigmoid_f(gv[3]) * tanhf(cn);
            g_c[b * Dq + d] = cn;
            g_h[b * Dq + d] = hn;

            if (t == Tq - 1) {
                float q = hn * __ldg(&fcf_w[d]) + sm.u.b.ctx[d] * __ldg(&fcf_w[Dq + d]);
#pragma unroll
                for (int o = 16; o; o >>= 1) q += __shfl_xor_sync(0xffffffffu, q, o);
                __syncthreads();
                if (lane == 0) sm.u.b.red[warp] = q;
                __syncthreads();
                if (tid == 0) {
                    float tot = 0.f;
#pragma unroll
                    for (int w = 0; w < 8; w++) tot += sm.u.b.red[w];
                    out[b] = tot + fcf_b[0];
                }
            }
        }
        gridbar();
    }
}

__global__ void prep_kernel(const float* __restrict__ w_hh,
                            const float* __restrict__ b_ih,
                            const float* __restrict__ b_hh)
{
    int i = blockIdx.x * blockDim.x + threadIdx.x;
    if (i < G4 * Dq) {
        int j = i >> 8, k = i & 255;
        g_whhT[(size_t)k * G4 + j] = w_hh[i];
    }
    if (i < G4) g_bsum[i] = b_ih[i] + b_hh[i];
    if (i < Bq * Dq) { g_h[i] = 0.f; g_c[i] = 0.f; }
    if (i < NLEAF * 32) g_cnt[i] = 0u;
    if (i == 0) { g_master = 0u; g_gen = 0u; }
}

// encfc[b,t] = enc[b,t,:] . fc_w[0:256]   (one warp per (b,t))
__global__ void __launch_bounds__(256) encfc_kernel(
        const float* __restrict__ enc, const float* __restrict__ fc_w)
{
    int w = blockIdx.x * 8 + (threadIdx.x >> 5);
    int lane = threadIdx.x & 31;
    const float4* p = (const float4*)(enc + (size_t)w * Eq);
    const float4* q = (const float4*)fc_w;
    float s = 0.f;
#pragma unroll
    for (int j = 0; j < 2; j++) {
        float4 e = __ldcg(p + lane + 32 * j);
        float4 f = __ldg(q + lane + 32 * j);
        s += e.x * f.x + e.y * f.y + e.z * f.z + e.w * f.w;
    }
#pragma unroll
    for (int o = 16; o; o >>= 1) s += __shfl_xor_sync(0xffffffffu, s, o);
    if (lane == 0) g_encfc[w] = s;
}

__global__ void __launch_bounds__(256) pre_gemm_kernel(
        const float* __restrict__ enc, const float* __restrict__ attn_w1,
        const float* __restrict__ attn_b1)
{
    __shared__ SmA2 sa;
    int mt = blockIdx.x >> 2, nt = blockIdx.x & 3;
    gemm128x64<__half>(&sa,
        enc + (size_t)mt * 128 * Eq, Eq,
        attn_w1 + (size_t)(2 * Dq) * Eq + nt * 64, Eq,
        g_pre + (size_t)mt * 128 * Eq + nt * 64, Eq, 256,
        attn_b1 + nt * 64);
}

extern "C" void kernel_launch(void* const* d_in, const int* in_sizes, int n_in,
                              void* d_out, int out_size)
{
    const float* enc     = (const float*)d_in[0];
    const float* yhist   = (const float*)d_in[1];
    const float* attn_w1 = (const float*)d_in[2];
    const float* attn_b1 = (const float*)d_in[3];
    const float* attn_w2 = (const float*)d_in[4];
    // d_in[5] = attn_b2: unused (softmax is shift-invariant)
    const float* w_ih    = (const float*)d_in[6];
    const float* w_hh    = (const float*)d_in[7];
    const float* b_ih    = (const float*)d_in[8];
    const float* b_hh    = (const float*)d_in[9];
    const float* fc_w    = (const float*)d_in[10];
    const float* fc_b    = (const float*)d_in[11];
    const float* fcf_w   = (const float*)d_in[12];
    const float* fcf_b   = (const float*)d_in[13];
    float* out = (float*)d_out;

    prep_kernel<<<1024, 256>>>(w_hh, b_ih, b_hh);
    encfc_kernel<<<BT / 8, 256>>>(enc, fc_w);
    pre_gemm_kernel<<<2048, 256>>>(enc, attn_w1, attn_b1);
    decoder_persist<<<NBLK, 256>>>(enc, yhist, attn_w1, attn_w2, w_ih,
                                   fc_w, fc_b, fcf_w, fcf_b, out);
}

// round 13
// speedup vs baseline: 1.2355x; 1.2355x over previous
#include <cuda_runtime.h>
#include <cuda_fp16.h>

#define Bq 512
#define Tq 128
#define Eq 256
#define Dq 256
#define G4 1024
#define BT (Bq*Tq)
#define NBLK 512
#define NLEAF 16
#define PER_LEAF 32   // 512 = 16*32

// ---------------- static device scratch ----------------
__device__ __half g_pre[(size_t)BT * Eq];     // enc @ W1_enc + b1 (fp16, 32MB)
__device__ float g_encfc[BT];                 // enc[b,t,:] . fc_w[0:256]
__device__ float g_whhT[Dq * G4];             // w_hh transposed [k][gate*256+d]
__device__ float g_bsum[G4];
__device__ float g_h[Bq * Dq];
__device__ float g_c[Bq * Dq];
__device__ float g_hp[16 * Bq * Eq];          // 16 K-partials of [h|c]@W1_hc
__device__ float g_gp[4 * (size_t)Bq * G4];   // 4 K-partials of h@w_hhT
__device__ unsigned g_cnt[NLEAF * 32];
__device__ unsigned g_master;
__device__ volatile unsigned g_gen;

struct SmA { float As[16][136]; float Bs[16][68]; };   // R11 engine layout
struct SmB {
    float hp[256]; unsigned hp2[128]; float sc[128]; float ctxp[8][256];
    float ctx[256]; float red[8]; float misc[4];
};
struct SmAll { union { SmA a; SmB b; } u; float w2s[256]; };

__device__ __forceinline__ unsigned tanh_h2(unsigned x) {
    unsigned y; asm("tanh.approx.f16x2 %0, %1;" : "=r"(y) : "r"(x)); return y;
}
__device__ __forceinline__ float sigmoid_f(float x) {
    return __fdividef(1.0f, 1.0f + __expf(-x));
}

// packed dual-fp32 FMA
#define FMA_X2(acc, a, b) \
    asm("fma.rn.f32x2 %0, %1, %2, %0;" : "+l"(acc) : "l"(a), "l"(b))

__device__ __forceinline__ unsigned long long pack2(float lo, float hi) {
    unsigned long long r;
    asm("mov.b64 %0, {%1, %2};" : "=l"(r) : "f"(lo), "f"(hi));
    return r;
}
__device__ __forceinline__ float2 unpack2(unsigned long long v) {
    float lo, hi;
    asm("mov.b64 {%0, %1}, %2;" : "=f"(lo), "=f"(hi) : "l"(v));
    return make_float2(lo, hi);
}

// 128x64 output tile, K multiple of 16, 256 threads, 8x4 microtile.
// R11 engine: single-buffered, FFMA2 with in-loop B packs.
// A mutable -> __ldcg; B immutable -> __ldg.
template<typename TO>
__device__ __forceinline__ void gemm128x64(SmA* s,
        const float* __restrict__ A, int lda,
        const float* __restrict__ Bm, int ldb,
        TO* __restrict__ C, int ldc, int K,
        const float* __restrict__ bias)
{
    const int tid = threadIdx.x;
    const int ty = tid >> 4, tx = tid & 15;
    const int arow = tid >> 2, ac4 = (tid & 3) << 2;
    const int bk = tid >> 4, bc4 = (tid & 15) << 2;

    unsigned long long acc2[4][4];   // [row-pair p][col j]: rows (2p,2p+1)
#pragma unroll
    for (int p = 0; p < 4; p++)
#pragma unroll
        for (int j = 0; j < 4; j++) acc2[p][j] = 0ull;

    for (int k0 = 0; k0 < K; k0 += 16) {
        float4 av0 = __ldcg((const float4*)(A + (size_t)arow * lda + k0 + ac4));
        float4 av1 = __ldcg((const float4*)(A + (size_t)(arow + 64) * lda + k0 + ac4));
        float4 bv  = __ldg((const float4*)(Bm + (size_t)(k0 + bk) * ldb + bc4));
        s->As[ac4 + 0][arow] = av0.x; s->As[ac4 + 1][arow] = av0.y;
        s->As[ac4 + 2][arow] = av0.z; s->As[ac4 + 3][arow] = av0.w;
        s->As[ac4 + 0][arow + 64] = av1.x; s->As[ac4 + 1][arow + 64] = av1.y;
        s->As[ac4 + 2][arow + 64] = av1.z; s->As[ac4 + 3][arow + 64] = av1.w;
        *(float4*)&s->Bs[bk][bc4] = bv;
        __syncthreads();
#pragma unroll
        for (int k = 0; k < 16; k++) {
            const float2* ap = (const float2*)&s->As[k][ty << 3];
            float4 b4 = *(const float4*)&s->Bs[k][tx << 2];
            unsigned long long bd0 = pack2(b4.x, b4.x);
            unsigned long long bd1 = pack2(b4.y, b4.y);
            unsigned long long bd2 = pack2(b4.z, b4.z);
            unsigned long long bd3 = pack2(b4.w, b4.w);
#pragma unroll
            for (int p = 0; p < 4; p++) {
                float2 a2 = ap[p];
                unsigned long long av = pack2(a2.x, a2.y);
                FMA_X2(acc2[p][0], av, bd0);
                FMA_X2(acc2[p][1], av, bd1);
                FMA_X2(acc2[p][2], av, bd2);
                FMA_X2(acc2[p][3], av, bd3);
            }
        }
        __syncthreads();
    }
#pragma unroll
    for (int p = 0; p < 4; p++) {
        float2 v0 = unpack2(acc2[p][0]);
        float2 v1 = unpack2(acc2[p][1]);
        float2 v2 = unpack2(acc2[p][2]);
        float2 v3 = unpack2(acc2[p][3]);
        float r0[4] = {v0.x, v1.x, v2.x, v3.x};   // row 2p
        float r1[4] = {v0.y, v1.y, v2.y, v3.y};   // row 2p+1
        if (bias) {
#pragma unroll
            for (int j = 0; j < 4; j++) {
                float bj = bias[(tx << 2) + j];
                r0[j] += bj; r1[j] += bj;
            }
        }
        size_t off0 = (size_t)((ty << 3) + 2 * p) * ldc + (tx << 2);
        size_t off1 = off0 + ldc;
        if constexpr (sizeof(TO) == 2) {
            __half2 h00 = __floats2half2_rn(r0[0], r0[1]);
            __half2 h01 = __floats2half2_rn(r0[2], r0[3]);
            __half2 h10 = __floats2half2_rn(r1[0], r1[1]);
            __half2 h11 = __floats2half2_rn(r1[2], r1[3]);
            uint2 u0; u0.x = *(unsigned*)&h00; u0.y = *(unsigned*)&h01;
            uint2 u1; u1.x = *(unsigned*)&h10; u1.y = *(unsigned*)&h11;
            *(uint2*)((__half*)C + off0) = u0;
            *(uint2*)((__half*)C + off1) = u1;
        } else {
            *(float4*)((float*)C + off0) = make_float4(r0[0], r0[1], r0[2], r0[3]);
            *(float4*)((float*)C + off1) = make_float4(r1[0], r1[1], r1[2], r1[3]);
        }
    }
    __syncthreads();
}

// one uint4 (8 fp16 pre values) of the score dot-product, fp32 accumulate
__device__ __forceinline__ void score_u4(uint4 p, uint4 h,
        float4 wa, float4 wb, float& acc)
{
    const __half2* ph = (const __half2*)&p;
    const __half2* hh = (const __half2*)&h;
    __half2 x0 = __hadd2(ph[0], hh[0]);
    __half2 x1 = __hadd2(ph[1], hh[1]);
    __half2 x2 = __hadd2(ph[2], hh[2]);
    __half2 x3 = __hadd2(ph[3], hh[3]);
    unsigned t0 = tanh_h2(*(unsigned*)&x0);
    unsigned t1 = tanh_h2(*(unsigned*)&x1);
    unsigned t2 = tanh_h2(*(unsigned*)&x2);
    unsigned t3 = tanh_h2(*(unsigned*)&x3);
    float2 f0 = __half22float2(*(const __half2*)&t0);
    float2 f1 = __half22float2(*(const __half2*)&t1);
    float2 f2 = __half22float2(*(const __half2*)&t2);
    float2 f3 = __half22float2(*(const __half2*)&t3);
    acc = fmaf(wa.x, f0.x, acc); acc = fmaf(wa.y, f0.y, acc);
    acc = fmaf(wa.z, f1.x, acc); acc = fmaf(wa.w, f1.y, acc);
    acc = fmaf(wb.x, f2.x, acc); acc = fmaf(wb.y, f2.y, acc);
    acc = fmaf(wb.z, f3.x, acc); acc = fmaf(wb.w, f3.y, acc);
}

__device__ __forceinline__ void gridbar() {
    __threadfence();
    __syncthreads();
    if (threadIdx.x == 0) {
        unsigned gen = g_gen;
        unsigned leaf = (blockIdx.x & (NLEAF - 1)) * 32;
        unsigned v = atomicAdd(&g_cnt[leaf], 1u) + 1u;
        if (v == (gen + 1u) * PER_LEAF) {
            unsigned m = atomicAdd(&g_master, 1u) + 1u;
            if (m == (gen + 1u) * NLEAF) {
                __threadfence();
                g_gen = gen + 1u;
            } else {
                while (g_gen == gen) __nanosleep(32);
            }
        } else {
            while (g_gen == gen) __nanosleep(64);
        }
        __threadfence();
    }
    __syncthreads();
}

__global__ void __launch_bounds__(256, 4) decoder_persist(
        const float* __restrict__ enc, const float* __restrict__ yhist,
        const float* __restrict__ attn_w1, const float* __restrict__ attn_w2,
        const float* __restrict__ w_ih,
        const float* __restrict__ fc_w, const float* __restrict__ fc_b,
        const float* __restrict__ fcf_w, const float* __restrict__ fcf_b,
        float* __restrict__ out)
{
    __shared__ SmAll sm;
    const int bid = blockIdx.x;
    const int tid = threadIdx.x;
    const int lane = tid & 31, warp = tid >> 5;
    const int b = bid;

    sm.w2s[tid] = __ldg(&attn_w2[tid]);   // immutable; first gemm sync covers it

    for (int t = 0; t < Tq; t++) {
        // ============ phase 1: step-GEMM partials, one unit per block ============
        if (bid < 256) {
            // gp unit: h @ w_hhT, tile 128x64, K-chunk 64 -> 4 partials
            int kq = bid & 3, tile = bid >> 2;
            int mt = tile >> 4, nt = tile & 15;
            gemm128x64<float>(&sm.u.a,
                g_h + (size_t)mt * 128 * Dq + kq * 64, Dq,
                g_whhT + (size_t)(kq * 64) * G4 + nt * 64, G4,
                g_gp + (size_t)kq * (Bq * G4) + (size_t)mt * 128 * G4 + nt * 64, G4,
                64, (const float*)0);
        } else {
            // hp unit: [h|c] @ W1_hc, tile 128x64, K-chunk 32 -> 16 partials
            int u = bid - 256;
            int tile = u >> 4, kq = u & 15;
            int mt = tile >> 2, nt = tile & 3;
            const float* A = (kq < 8 ? g_h + kq * 32 : g_c + (kq - 8) * 32)
                             + (size_t)mt * 128 * Dq;
            gemm128x64<float>(&sm.u.a, A, Dq,
                attn_w1 + (size_t)(kq * 32) * Eq + nt * 64, Eq,
                g_hp + (size_t)kq * (Bq * Eq) + (size_t)mt * 128 * Eq + nt * 64, Eq,
                32, (const float*)0);
        }
        gridbar();

        // ============ phase 2: attention + LSTM, row-local (row b = bid) ============
        {
            float hpv = 0.f;
#pragma unroll
            for (int q = 0; q < 16; q++)
                hpv += __ldcg(&g_hp[(size_t)q * (Bq * Eq) + b * Eq + tid]);
            sm.u.b.hp[tid] = hpv;
            __syncthreads();
            if (tid < 128) {
                __half2 h2 = __floats2half2_rn(sm.u.b.hp[2 * tid], sm.u.b.hp[2 * tid + 1]);
                sm.u.b.hp2[tid] = *(unsigned*)&h2;
            }
            __syncthreads();

            // scores: one thread per (t, half); coalesced loads, no shuffles
            {
                int ttt = tid & 127, hf = tid >> 7;
                const uint4* prow = (const uint4*)(g_pre + ((size_t)b * Tq + ttt) * Eq)
                                    + (hf << 4);
                float acc = 0.f;
#pragma unroll
                for (int i = 0; i < 4; i++) {
                    uint4 p0 = __ldg(prow + (i << 2) + 0);
                    uint4 p1 = __ldg(prow + (i << 2) + 1);
                    uint4 p2 = __ldg(prow + (i << 2) + 2);
                    uint4 p3 = __ldg(prow + (i << 2) + 3);
                    const uint4* hpq = (const uint4*)&sm.u.b.hp2[(hf << 6) + (i << 4)];
                    const float4* wq = (const float4*)&sm.w2s[(hf << 7) + (i << 5)];
                    score_u4(p0, hpq[0], wq[0], wq[1], acc);
                    score_u4(p1, hpq[1], wq[2], wq[3], acc);
                    score_u4(p2, hpq[2], wq[4], wq[5], acc);
                    score_u4(p3, hpq[3], wq[6], wq[7], acc);
                }
                sm.u.b.ctxp[hf][ttt] = acc;
            }
            __syncthreads();

            // softmax over T=128 (attn_b2 dropped: shift-invariant)
            float sv = (tid < Tq) ? sm.u.b.ctxp[0][tid] + sm.u.b.ctxp[1][tid] : -3.0e38f;
            float m = sv;
#pragma unroll
            for (int o = 16; o; o >>= 1) m = fmaxf(m, __shfl_xor_sync(0xffffffffu, m, o));
            if (lane == 0) sm.u.b.red[warp] = m;
            __syncthreads();
            if (tid == 0) {
                float mm = sm.u.b.red[0];
#pragma unroll
                for (int w = 1; w < 8; w++) mm = fmaxf(mm, sm.u.b.red[w]);
                sm.u.b.misc[0] = mm;
            }
            __syncthreads();
            float ex = (tid < Tq) ? __expf(sv - sm.u.b.misc[0]) : 0.f;
            float ss = ex;
#pragma unroll
            for (int o = 16; o; o >>= 1) ss += __shfl_xor_sync(0xffffffffu, ss, o);
            if (lane == 0) sm.u.b.red[warp] = ss;
            __syncthreads();
            if (tid == 0) {
                float tot = 0.f;
#pragma unroll
                for (int w = 0; w < 8; w++) tot += sm.u.b.red[w];
                sm.u.b.misc[1] = __fdividef(1.0f, tot);
            }
            if (tid < Tq) sm.u.b.sc[tid] = ex;
            __syncthreads();
            float invs = sm.u.b.misc[1];

            // y_dot = sum_t ex[t] * encfc[b,t]
            float yd = (tid < Tq) ? sm.u.b.sc[tid] * __ldg(&g_encfc[b * Tq + tid]) : 0.f;
#pragma unroll
            for (int o = 16; o; o >>= 1) yd += __shfl_xor_sync(0xffffffffu, yd, o);
            if (lane == 0) sm.u.b.red[warp] = yd;
            __syncthreads();
            if (tid == 0) {
                float tot = 0.f;
#pragma unroll
                for (int w = 0; w < 8; w++) tot += sm.u.b.red[w];
                sm.u.b.misc[2] = tot * invs + __ldg(&yhist[b * Tq + t]) * fc_w[256] + fc_b[0];
            }

            // full ctx only at the final step (for fc_final)
            if (t == Tq - 1) {
                float a8[8] = {0.f, 0.f, 0.f, 0.f, 0.f, 0.f, 0.f, 0.f};
                const float4* encb = (const float4*)(enc + (size_t)b * Tq * Eq);
#pragma unroll 2
                for (int i = 0; i < 16; i++) {
                    int tt = (warp << 4) + i;
                    float wgt = sm.u.b.sc[tt];
                    float4 e0 = __ldg(encb + (size_t)tt * 64 + lane * 2);
                    float4 e1 = __ldg(encb + (size_t)tt * 64 + lane * 2 + 1);
                    a8[0] = fmaf(wgt, e0.x, a8[0]); a8[1] = fmaf(wgt, e0.y, a8[1]);
                    a8[2] = fmaf(wgt, e0.z, a8[2]); a8[3] = fmaf(wgt, e0.w, a8[3]);
                    a8[4] = fmaf(wgt, e1.x, a8[4]); a8[5] = fmaf(wgt, e1.y, a8[5]);
                    a8[6] = fmaf(wgt, e1.z, a8[6]); a8[7] = fmaf(wgt, e1.w, a8[7]);
                }
                __syncthreads();
#pragma unroll
                for (int j = 0; j < 8; j++) sm.u.b.ctxp[warp][lane * 8 + j] = a8[j];
                __syncthreads();
                float cv = 0.f;
#pragma unroll
                for (int w = 0; w < 8; w++) cv += sm.u.b.ctxp[w][tid];
                sm.u.b.ctx[tid] = cv * invs;
            }
            __syncthreads();

            // LSTM epilogue (thread = d)
            float yt = sm.u.b.misc[2];
            int d = tid;
            float gv[4];
#pragma unroll
            for (int g = 0; g < 4; g++) {
                float a = fmaf(yt, __ldg(&w_ih[g * 256 + d]), g_bsum[g * 256 + d]);
#pragma unroll
                for (int kq = 0; kq < 4; kq++)
                    a += __ldcg(&g_gp[(size_t)kq * (Bq * G4) + (size_t)b * G4 + g * 256 + d]);
                gv[g] = a;
            }
            float cprev = __ldcg(&g_c[b * Dq + d]);
            float cn = sigmoid_f(gv[1]) * cprev + sigmoid_f(gv[0]) * tanhf(gv[2]);
            float hn = sigmoid_f(gv[3]) * tanhf(cn);
            g_c[b * Dq + d] = cn;
            g_h[b * Dq + d] = hn;

            if (t == Tq - 1) {
                float q = hn * __ldg(&fcf_w[d]) + sm.u.b.ctx[d] * __ldg(&fcf_w[Dq + d]);
#pragma unroll
                for (int o = 16; o; o >>= 1) q += __shfl_xor_sync(0xffffffffu, q, o);
                __syncthreads();
                if (lane == 0) sm.u.b.red[warp] = q;
                __syncthreads();
                if (tid == 0) {
                    float tot = 0.f;
#pragma unroll
                    for (int w = 0; w < 8; w++) tot += sm.u.b.red[w];
                    out[b] = tot + fcf_b[0];
                }
            }
        }
        gridbar();
    }
}

__global__ void prep_kernel(const float* __restrict__ w_hh,
                            const float* __restrict__ b_ih,
                            const float* __restrict__ b_hh)
{
    int i = blockIdx.x * blockDim.x + threadIdx.x;
    if (i < G4 * Dq) {
        int j = i >> 8, k = i & 255;
        g_whhT[(size_t)k * G4 + j] = w_hh[i];
    }
    if (i < G4) g_bsum[i] = b_ih[i] + b_hh[i];
    if (i < Bq * Dq) { g_h[i] = 0.f; g_c[i] = 0.f; }
    if (i < NLEAF * 32) g_cnt[i] = 0u;
    if (i == 0) { g_master = 0u; g_gen = 0u; }
}

// encfc[b,t] = enc[b,t,:] . fc_w[0:256]   (one warp per (b,t))
__global__ void __launch_bounds__(256) encfc_kernel(
        const float* __restrict__ enc, const float* __restrict__ fc_w)
{
    int w = blockIdx.x * 8 + (threadIdx.x >> 5);
    int lane = threadIdx.x & 31;
    const float4* p = (const float4*)(enc + (size_t)w * Eq);
    const float4* q = (const float4*)fc_w;
    float s = 0.f;
#pragma unroll
    for (int j = 0; j < 2; j++) {
        float4 e = __ldcg(p + lane + 32 * j);
        float4 f = __ldg(q + lane + 32 * j);
        s += e.x * f.x + e.y * f.y + e.z * f.z + e.w * f.w;
    }
#pragma unroll
    for (int o = 16; o; o >>= 1) s += __shfl_xor_sync(0xffffffffu, s, o);
    if (lane == 0) g_encfc[w] = s;
}

__global__ void __launch_bounds__(256) pre_gemm_kernel(
        const float* __restrict__ enc, const float* __restrict__ attn_w1,
        const float* __restrict__ attn_b1)
{
    __shared__ SmA sa;
    int mt = blockIdx.x >> 2, nt = blockIdx.x & 3;
    gemm128x64<__half>(&sa,
        enc + (size_t)mt * 128 * Eq, Eq,
        attn_w1 + (size_t)(2 * Dq) * Eq + nt * 64, Eq,
        g_pre + (size_t)mt * 128 * Eq + nt * 64, Eq, 256,
        attn_b1 + nt * 64);
}

extern "C" void kernel_launch(void* const* d_in, const int* in_sizes, int n_in,
                              void* d_out, int out_size)
{
    const float* enc     = (const float*)d_in[0];
    const float* yhist   = (const float*)d_in[1];
    const float* attn_w1 = (const float*)d_in[2];
    const float* attn_b1 = (const float*)d_in[3];
    const float* attn_w2 = (const float*)d_in[4];
    // d_in[5] = attn_b2: unused (softmax is shift-invariant)
    const float* w_ih    = (const float*)d_in[6];
    const float* w_hh    = (const float*)d_in[7];
    const float* b_ih    = (const float*)d_in[8];
    const float* b_hh    = (const float*)d_in[9];
    const float* fc_w    = (const float*)d_in[10];
    const float* fc_b    = (const float*)d_in[11];
    const float* fcf_w   = (const float*)d_in[12];
    const float* fcf_b   = (const float*)d_in[13];
    float* out = (float*)d_out;

    prep_kernel<<<1024, 256>>>(w_hh, b_ih, b_hh);
    encfc_kernel<<<BT / 8, 256>>>(enc, fc_w);
    pre_gemm_kernel<<<2048, 256>>>(enc, attn_w1, attn_b1);
    decoder_persist<<<NBLK, 256>>>(enc, yhist, attn_w1, attn_w2, w_ih,
                                   fc_w, fc_b, fcf_w, fcf_b, out);
}

// round 14
// speedup vs baseline: 1.5733x; 1.2733x over previous
#include <cuda_runtime.h>
#include <cuda_fp16.h>

#define Bq 512
#define Tq 128
#define Eq 256
#define Dq 256
#define G4 1024
#define BT (Bq*Tq)
#define NBLK 512
#define NLEAF 16
#define PER_LEAF 32   // 512 = 16*32

// ---------------- static device scratch ----------------
__device__ __half g_pre[(size_t)BT * Eq];     // enc @ W1_enc + b1 (fp16, 32MB)
__device__ float g_encfc[BT];                 // enc[b,t,:] . fc_w[0:256]
__device__ float g_whhT[Dq * G4];             // w_hh transposed [k][gate*256+d]
__device__ float g_bsum[G4];
__device__ float g_h[Bq * Dq];
__device__ float g_c[Bq * Dq];
__device__ float g_hp[16 * Bq * Eq];          // 16 K-partials of [h|c]@W1_hc
__device__ float g_gp[4 * (size_t)Bq * G4];   // 4 K-partials of h@w_hhT
__device__ unsigned g_cnt[NLEAF * 32];
__device__ unsigned g_master;
__device__ volatile unsigned g_gen;

struct SmA { float As[16][136]; float Bs[16][68]; };   // prepass engine layout
struct SmStep { float As[16][132]; };                  // step engine: A slab only
struct SmB {
    float hp[256]; unsigned hp2[128]; float sc[128]; float ctxp[8][256];
    float ctx[256]; float red[8]; float misc[4];
};
struct SmAll {
    union { SmStep a; SmB b; SmA pp; } u;
    float Bper[64][68];                                // persistent B tile (<=16KB used)
};

__device__ __forceinline__ unsigned tanh_h2(unsigned x) {
    unsigned y; asm("tanh.approx.f16x2 %0, %1;" : "=r"(y) : "r"(x)); return y;
}
__device__ __forceinline__ float sigmoid_f(float x) {
    return __fdividef(1.0f, 1.0f + __expf(-x));
}

// packed dual-fp32 FMA
#define FMA_X2(acc, a, b) \
    asm("fma.rn.f32x2 %0, %1, %2, %0;" : "+l"(acc) : "l"(a), "l"(b))

__device__ __forceinline__ unsigned long long pack2(float lo, float hi) {
    unsigned long long r;
    asm("mov.b64 %0, {%1, %2};" : "=l"(r) : "f"(lo), "f"(hi));
    return r;
}
__device__ __forceinline__ float2 unpack2(unsigned long long v) {
    float lo, hi;
    asm("mov.b64 {%0, %1}, %2;" : "=f"(lo), "=f"(hi) : "l"(v));
    return make_float2(lo, hi);
}

// ---------------- step GEMM: A staged per slab, B persistent in smem ----------------
// 128x64 tile, K in {32,64}, 256 threads, 8x4 microtile, FFMA2 accumulators.
__device__ __forceinline__ void step_gemm(SmAll* sm,
        const float* __restrict__ A, int lda,
        float* __restrict__ C, int ldc, int K)
{
    const int tid = threadIdx.x;
    const int ty = tid >> 4, tx = tid & 15;
    const int arow = tid >> 2, ac4 = (tid & 3) << 2;

    unsigned long long acc2[4][4];
#pragma unroll
    for (int p = 0; p < 4; p++)
#pragma unroll
        for (int j = 0; j < 4; j++) acc2[p][j] = 0ull;

    for (int k0 = 0; k0 < K; k0 += 16) {
        float4 av0 = __ldcg((const float4*)(A + (size_t)arow * lda + k0 + ac4));
        float4 av1 = __ldcg((const float4*)(A + (size_t)(arow + 64) * lda + k0 + ac4));
        sm->u.a.As[ac4 + 0][arow] = av0.x; sm->u.a.As[ac4 + 1][arow] = av0.y;
        sm->u.a.As[ac4 + 2][arow] = av0.z; sm->u.a.As[ac4 + 3][arow] = av0.w;
        sm->u.a.As[ac4 + 0][arow + 64] = av1.x; sm->u.a.As[ac4 + 1][arow + 64] = av1.y;
        sm->u.a.As[ac4 + 2][arow + 64] = av1.z; sm->u.a.As[ac4 + 3][arow + 64] = av1.w;
        __syncthreads();
#pragma unroll
        for (int k = 0; k < 16; k++) {
            ulonglong2 aLo = *(const ulonglong2*)&sm->u.a.As[k][ty << 3];
            ulonglong2 aHi = *(const ulonglong2*)&sm->u.a.As[k][(ty << 3) + 4];
            float4 b4 = *(const float4*)&sm->Bper[k0 + k][tx << 2];
            unsigned long long bd0 = pack2(b4.x, b4.x);
            unsigned long long bd1 = pack2(b4.y, b4.y);
            unsigned long long bd2 = pack2(b4.z, b4.z);
            unsigned long long bd3 = pack2(b4.w, b4.w);
            FMA_X2(acc2[0][0], aLo.x, bd0); FMA_X2(acc2[0][1], aLo.x, bd1);
            FMA_X2(acc2[0][2], aLo.x, bd2); FMA_X2(acc2[0][3], aLo.x, bd3);
            FMA_X2(acc2[1][0], aLo.y, bd0); FMA_X2(acc2[1][1], aLo.y, bd1);
            FMA_X2(acc2[1][2], aLo.y, bd2); FMA_X2(acc2[1][3], aLo.y, bd3);
            FMA_X2(acc2[2][0], aHi.x, bd0); FMA_X2(acc2[2][1], aHi.x, bd1);
            FMA_X2(acc2[2][2], aHi.x, bd2); FMA_X2(acc2[2][3], aHi.x, bd3);
            FMA_X2(acc2[3][0], aHi.y, bd0); FMA_X2(acc2[3][1], aHi.y, bd1);
            FMA_X2(acc2[3][2], aHi.y, bd2); FMA_X2(acc2[3][3], aHi.y, bd3);
        }
        __syncthreads();
    }

#pragma unroll
    for (int p = 0; p < 4; p++) {
        float2 v0 = unpack2(acc2[p][0]);
        float2 v1 = unpack2(acc2[p][1]);
        float2 v2 = unpack2(acc2[p][2]);
        float2 v3 = unpack2(acc2[p][3]);
        size_t off0 = (size_t)((ty << 3) + 2 * p) * ldc + (tx << 2);
        size_t off1 = off0 + ldc;
        *(float4*)(C + off0) = make_float4(v0.x, v1.x, v2.x, v3.x);
        *(float4*)(C + off1) = make_float4(v0.y, v1.y, v2.y, v3.y);
    }
}

// ---------------- prepass GEMM (R11 engine, unchanged) ----------------
template<typename TO>
__device__ __forceinline__ void gemm128x64(SmA* s,
        const float* __restrict__ A, int lda,
        const float* __restrict__ Bm, int ldb,
        TO* __restrict__ C, int ldc, int K,
        const float* __restrict__ bias)
{
    const int tid = threadIdx.x;
    const int ty = tid >> 4, tx = tid & 15;
    const int arow = tid >> 2, ac4 = (tid & 3) << 2;
    const int bk = tid >> 4, bc4 = (tid & 15) << 2;

    unsigned long long acc2[4][4];
#pragma unroll
    for (int p = 0; p < 4; p++)
#pragma unroll
        for (int j = 0; j < 4; j++) acc2[p][j] = 0ull;

    for (int k0 = 0; k0 < K; k0 += 16) {
        float4 av0 = __ldcg((const float4*)(A + (size_t)arow * lda + k0 + ac4));
        float4 av1 = __ldcg((const float4*)(A + (size_t)(arow + 64) * lda + k0 + ac4));
        float4 bv  = __ldg((const float4*)(Bm + (size_t)(k0 + bk) * ldb + bc4));
        s->As[ac4 + 0][arow] = av0.x; s->As[ac4 + 1][arow] = av0.y;
        s->As[ac4 + 2][arow] = av0.z; s->As[ac4 + 3][arow] = av0.w;
        s->As[ac4 + 0][arow + 64] = av1.x; s->As[ac4 + 1][arow + 64] = av1.y;
        s->As[ac4 + 2][arow + 64] = av1.z; s->As[ac4 + 3][arow + 64] = av1.w;
        *(float4*)&s->Bs[bk][bc4] = bv;
        __syncthreads();
#pragma unroll
        for (int k = 0; k < 16; k++) {
            const float2* ap = (const float2*)&s->As[k][ty << 3];
            float4 b4 = *(const float4*)&s->Bs[k][tx << 2];
            unsigned long long bd0 = pack2(b4.x, b4.x);
            unsigned long long bd1 = pack2(b4.y, b4.y);
            unsigned long long bd2 = pack2(b4.z, b4.z);
            unsigned long long bd3 = pack2(b4.w, b4.w);
#pragma unroll
            for (int p = 0; p < 4; p++) {
                float2 a2 = ap[p];
                unsigned long long av = pack2(a2.x, a2.y);
                FMA_X2(acc2[p][0], av, bd0);
                FMA_X2(acc2[p][1], av, bd1);
                FMA_X2(acc2[p][2], av, bd2);
                FMA_X2(acc2[p][3], av, bd3);
            }
        }
        __syncthreads();
    }
#pragma unroll
    for (int p = 0; p < 4; p++) {
        float2 v0 = unpack2(acc2[p][0]);
        float2 v1 = unpack2(acc2[p][1]);
        float2 v2 = unpack2(acc2[p][2]);
        float2 v3 = unpack2(acc2[p][3]);
        float r0[4] = {v0.x, v1.x, v2.x, v3.x};
        float r1[4] = {v0.y, v1.y, v2.y, v3.y};
        if (bias) {
#pragma unroll
            for (int j = 0; j < 4; j++) {
                float bj = bias[(tx << 2) + j];
                r0[j] += bj; r1[j] += bj;
            }
        }
        size_t off0 = (size_t)((ty << 3) + 2 * p) * ldc + (tx << 2);
        size_t off1 = off0 + ldc;
        if constexpr (sizeof(TO) == 2) {
            __half2 h00 = __floats2half2_rn(r0[0], r0[1]);
            __half2 h01 = __floats2half2_rn(r0[2], r0[3]);
            __half2 h10 = __floats2half2_rn(r1[0], r1[1]);
            __half2 h11 = __floats2half2_rn(r1[2], r1[3]);
            uint2 u0; u0.x = *(unsigned*)&h00; u0.y = *(unsigned*)&h01;
            uint2 u1; u1.x = *(unsigned*)&h10; u1.y = *(unsigned*)&h11;
            *(uint2*)((__half*)C + off0) = u0;
            *(uint2*)((__half*)C + off1) = u1;
        } else {
            *(float4*)((float*)C + off0) = make_float4(r0[0], r0[1], r0[2], r0[3]);
            *(float4*)((float*)C + off1) = make_float4(r1[0], r1[1], r1[2], r1[3]);
        }
    }
    __syncthreads();
}

__device__ __forceinline__ void gridbar() {
    __threadfence();
    __syncthreads();
    if (threadIdx.x == 0) {
        unsigned gen = g_gen;
        unsigned leaf = (blockIdx.x & (NLEAF - 1)) * 32;
        unsigned v = atomicAdd(&g_cnt[leaf], 1u) + 1u;
        if (v == (gen + 1u) * PER_LEAF) {
            unsigned m = atomicAdd(&g_master, 1u) + 1u;
            if (m == (gen + 1u) * NLEAF) {
                __threadfence();
                g_gen = gen + 1u;
            } else {
                while (g_gen == gen) __nanosleep(32);
            }
        } else {
            while (g_gen == gen) __nanosleep(64);
        }
        __threadfence();
    }
    __syncthreads();
}

__global__ void __launch_bounds__(256, 4) decoder_persist(
        const float* __restrict__ enc, const float* __restrict__ yhist,
        const float* __restrict__ attn_w1, const float* __restrict__ attn_w2,
        const float* __restrict__ w_ih,
        const float* __restrict__ fc_w, const float* __restrict__ fc_b,
        const float* __restrict__ fcf_w, const float* __restrict__ fcf_b,
        float* __restrict__ out)
{
    __shared__ SmAll sm;
    const int bid = blockIdx.x;
    const int tid = threadIdx.x;
    const int lane = tid & 31, warp = tid >> 5;
    const int b = bid;

    // ---- unit geometry + persistent B tile load (once) ----
    const float* Abase; int lda; float* Cbase; int ldc; int Kdim;
    {
        const float* Bm; int ldb; int Krows;
        if (bid < 256) {
            int kq = bid & 3, tile = bid >> 2;
            int mt = tile >> 4, nt = tile & 15;
            Abase = g_h + (size_t)mt * 128 * Dq + kq * 64; lda = Dq;
            Bm = g_whhT + (size_t)(kq * 64) * G4 + nt * 64; ldb = G4; Krows = 64;
            Cbase = g_gp + (size_t)kq * (Bq * G4) + (size_t)mt * 128 * G4 + nt * 64;
            ldc = G4; Kdim = 64;
        } else {
            int u = bid - 256;
            int tile = u >> 4, kq = u & 15;
            int mt = tile >> 2, nt = tile & 3;
            Abase = (kq < 8 ? g_h + kq * 32 : g_c + (kq - 8) * 32)
                    + (size_t)mt * 128 * Dq; lda = Dq;
            Bm = attn_w1 + (size_t)(kq * 32) * Eq + nt * 64; ldb = Eq; Krows = 32;
            Cbase = g_hp + (size_t)kq * (Bq * Eq) + (size_t)mt * 128 * Eq + nt * 64;
            ldc = Eq; Kdim = 32;
        }
        for (int i = tid; i < Krows * 16; i += 256) {
            int kk = i >> 4, c4 = (i & 15) << 2;
            *(float4*)&sm.Bper[kk][c4] = __ldg((const float4*)(Bm + (size_t)kk * ldb + c4));
        }
        __syncthreads();
    }

    for (int t = 0; t < Tq; t++) {
        // ============ phase 1: step-GEMM partial (persistent B) ============
        step_gemm(&sm, Abase, lda, Cbase, ldc, Kdim);
        gridbar();

        // ============ phase 2: attention + LSTM, row-local (row b = bid) ============
        {
            float hpv = 0.f;
#pragma unroll
            for (int q = 0; q < 16; q++)
                hpv += __ldcg(&g_hp[(size_t)q * (Bq * Eq) + b * Eq + tid]);
            sm.u.b.hp[tid] = hpv;
            __syncthreads();
            if (tid < 128) {
                __half2 h2 = __floats2half2_rn(sm.u.b.hp[2 * tid], sm.u.b.hp[2 * tid + 1]);
                sm.u.b.hp2[tid] = *(unsigned*)&h2;
            }
            __syncthreads();

            unsigned hp2r[4];
            float w2r[8];
#pragma unroll
            for (int q = 0; q < 4; q++) hp2r[q] = sm.u.b.hp2[lane * 4 + q];
#pragma unroll
            for (int j = 0; j < 8; j++) w2r[j] = __ldg(&attn_w2[lane * 8 + j]);

            // scores: 8 warps x 16 t's, 4 loads in flight; tanh in f16x2
            const uint4* preb = (const uint4*)(g_pre + (size_t)b * Tq * Eq);
#pragma unroll
            for (int tb = 0; tb < 4; tb++) {
                int tt0 = warp + tb * 32;
                uint4 pv[4];
#pragma unroll
                for (int j = 0; j < 4; j++)
                    pv[j] = __ldg(preb + (size_t)(tt0 + j * 8) * 32 + lane);
#pragma unroll
                for (int j = 0; j < 4; j++) {
                    const unsigned* ph = (const unsigned*)&pv[j];
                    float a = 0.f;
#pragma unroll
                    for (int q = 0; q < 4; q++) {
                        __half2 x = *(const __half2*)&ph[q] + *(const __half2*)&hp2r[q];
                        unsigned th = tanh_h2(*(unsigned*)&x);
                        float2 f = __half22float2(*(const __half2*)&th);
                        a = fmaf(w2r[2 * q], f.x, a);
                        a = fmaf(w2r[2 * q + 1], f.y, a);
                    }
#pragma unroll
                    for (int o = 16; o; o >>= 1) a += __shfl_xor_sync(0xffffffffu, a, o);
                    if (lane == 0) sm.u.b.sc[tt0 + j * 8] = a;
                }
            }
            __syncthreads();

            // softmax over T=128 (attn_b2 dropped: shift-invariant)
            float sv = (tid < Tq) ? sm.u.b.sc[tid] : -3.0e38f;
            float m = sv;
#pragma unroll
            for (int o = 16; o; o >>= 1) m = fmaxf(m, __shfl_xor_sync(0xffffffffu, m, o));
            if (lane == 0) sm.u.b.red[warp] = m;
            __syncthreads();
            if (tid == 0) {
                float mm = sm.u.b.red[0];
#pragma unroll
                for (int w = 1; w < 8; w++) mm = fmaxf(mm, sm.u.b.red[w]);
                sm.u.b.misc[0] = mm;
            }
            __syncthreads();
            float ex = (tid < Tq) ? __expf(sv - sm.u.b.misc[0]) : 0.f;
            float ss = ex;
#pragma unroll
            for (int o = 16; o; o >>= 1) ss += __shfl_xor_sync(0xffffffffu, ss, o);
            if (lane == 0) sm.u.b.red[warp] = ss;
            __syncthreads();
            if (tid == 0) {
                float tot = 0.f;
#pragma unroll
                for (int w = 0; w < 8; w++) tot += sm.u.b.red[w];
                sm.u.b.misc[1] = __fdividef(1.0f, tot);
            }
            if (tid < Tq) sm.u.b.sc[tid] = ex;
            __syncthreads();
            float invs = sm.u.b.misc[1];

            // y_dot = sum_t ex[t] * encfc[b,t]
            float yd = (tid < Tq) ? sm.u.b.sc[tid] * __ldg(&g_encfc[b * Tq + tid]) : 0.f;
#pragma unroll
            for (int o = 16; o; o >>= 1) yd += __shfl_xor_sync(0xffffffffu, yd, o);
            if (lane == 0) sm.u.b.red[warp] = yd;
            __syncthreads();
            if (tid == 0) {
                float tot = 0.f;
#pragma unroll
                for (int w = 0; w < 8; w++) tot += sm.u.b.red[w];
                sm.u.b.misc[2] = tot * invs + __ldg(&yhist[b * Tq + t]) * fc_w[256] + fc_b[0];
            }

            // full ctx only at the final step (for fc_final)
            if (t == Tq - 1) {
                float a8[8] = {0.f, 0.f, 0.f, 0.f, 0.f, 0.f, 0.f, 0.f};
                const float4* encb = (const float4*)(enc + (size_t)b * Tq * Eq);
#pragma unroll 2
                for (int i = 0; i < 16; i++) {
                    int tt = (warp << 4) + i;
                    float wgt = sm.u.b.sc[tt];
                    float4 e0 = __ldg(encb + (size_t)tt * 64 + lane * 2);
                    float4 e1 = __ldg(encb + (size_t)tt * 64 + lane * 2 + 1);
                    a8[0] = fmaf(wgt, e0.x, a8[0]); a8[1] = fmaf(wgt, e0.y, a8[1]);
                    a8[2] = fmaf(wgt, e0.z, a8[2]); a8[3] = fmaf(wgt, e0.w, a8[3]);
                    a8[4] = fmaf(wgt, e1.x, a8[4]); a8[5] = fmaf(wgt, e1.y, a8[5]);
                    a8[6] = fmaf(wgt, e1.z, a8[6]); a8[7] = fmaf(wgt, e1.w, a8[7]);
                }
                __syncthreads();
#pragma unroll
                for (int j = 0; j < 8; j++) sm.u.b.ctxp[warp][lane * 8 + j] = a8[j];
                __syncthreads();
                float cv = 0.f;
#pragma unroll
                for (int w = 0; w < 8; w++) cv += sm.u.b.ctxp[w][tid];
                sm.u.b.ctx[tid] = cv * invs;
            }
            __syncthreads();

            // LSTM epilogue (thread = d)
            float yt = sm.u.b.misc[2];
            int d = tid;
            float gv[4];
#pragma unroll
            for (int g = 0; g < 4; g++) {
                float a = fmaf(yt, __ldg(&w_ih[g * 256 + d]), g_bsum[g * 256 + d]);
#pragma unroll
                for (int kq = 0; kq < 4; kq++)
                    a += __ldcg(&g_gp[(size_t)kq * (Bq * G4) + (size_t)b * G4 + g * 256 + d]);
                gv[g] = a;
            }
            float cprev = __ldcg(&g_c[b * Dq + d]);
            float cn = sigmoid_f(gv[1]) * cprev + sigmoid_f(gv[0]) * tanhf(gv[2]);
            float hn = sigmoid_f(gv[3]) * tanhf(cn);
            g_c[b * Dq + d] = cn;
            g_h[b * Dq + d] = hn;

            if (t == Tq - 1) {
                float q = hn * __ldg(&fcf_w[d]) + sm.u.b.ctx[d] * __ldg(&fcf_w[Dq + d]);
#pragma unroll
                for (int o = 16; o; o >>= 1) q += __shfl_xor_sync(0xffffffffu, q, o);
                __syncthreads();
                if (lane == 0) sm.u.b.red[warp] = q;
                __syncthreads();
                if (tid == 0) {
                    float tot = 0.f;
#pragma unroll
                    for (int w = 0; w < 8; w++) tot += sm.u.b.red[w];
                    out[b] = tot + fcf_b[0];
                }
            }
        }
        gridbar();
    }
}

__global__ void prep_kernel(const float* __restrict__ w_hh,
                            const float* __restrict__ b_ih,
                            const float* __restrict__ b_hh)
{
    int i = blockIdx.x * blockDim.x + threadIdx.x;
    if (i < G4 * Dq) {
        int j = i >> 8, k = i & 255;
        g_whhT[(size_t)k * G4 + j] = w_hh[i];
    }
    if (i < G4) g_bsum[i] = b_ih[i] + b_hh[i];
    if (i < Bq * Dq) { g_h[i] = 0.f; g_c[i] = 0.f; }
    if (i < NLEAF * 32) g_cnt[i] = 0u;
    if (i == 0) { g_master = 0u; g_gen = 0u; }
}

// encfc[b,t] = enc[b,t,:] . fc_w[0:256]   (one warp per (b,t))
__global__ void __launch_bounds__(256) encfc_kernel(
        const float* __restrict__ enc, const float* __restrict__ fc_w)
{
    int w = blockIdx.x * 8 + (threadIdx.x >> 5);
    int lane = threadIdx.x & 31;
    const float4* p = (const float4*)(enc + (size_t)w * Eq);
    const float4* q = (const float4*)fc_w;
    float s = 0.f;
#pragma unroll
    for (int j = 0; j < 2; j++) {
        float4 e = __ldcg(p + lane + 32 * j);
        float4 f = __ldg(q + lane + 32 * j);
        s += e.x * f.x + e.y * f.y + e.z * f.z + e.w * f.w;
    }
#pragma unroll
    for (int o = 16; o; o >>= 1) s += __shfl_xor_sync(0xffffffffu, s, o);
    if (lane == 0) g_encfc[w] = s;
}

__global__ void __launch_bounds__(256) pre_gemm_kernel(
        const float* __restrict__ enc, const float* __restrict__ attn_w1,
        const float* __restrict__ attn_b1)
{
    __shared__ SmA sa;
    int mt = blockIdx.x >> 2, nt = blockIdx.x & 3;
    gemm128x64<__half>(&sa,
        enc + (size_t)mt * 128 * Eq, Eq,
        attn_w1 + (size_t)(2 * Dq) * Eq + nt * 64, Eq,
        g_pre + (size_t)mt * 128 * Eq + nt * 64, Eq, 256,
        attn_b1 + nt * 64);
}

extern "C" void kernel_launch(void* const* d_in, const int* in_sizes, int n_in,
                              void* d_out, int out_size)
{
    const float* enc     = (const float*)d_in[0];
    const float* yhist   = (const float*)d_in[1];
    const float* attn_w1 = (const float*)d_in[2];
    const float* attn_b1 = (const float*)d_in[3];
    const float* attn_w2 = (const float*)d_in[4];
    // d_in[5] = attn_b2: unused (softmax is shift-invariant)
    const float* w_ih    = (const float*)d_in[6];
    const float* w_hh    = (const float*)d_in[7];
    const float* b_ih    = (const float*)d_in[8];
    const float* b_hh    = (const float*)d_in[9];
    const float* fc_w    = (const float*)d_in[10];
    const float* fc_b    = (const float*)d_in[11];
    const float* fcf_w   = (const float*)d_in[12];
    const float* fcf_b   = (const float*)d_in[13];
    float* out = (float*)d_out;

    prep_kernel<<<1024, 256>>>(w_hh, b_ih, b_hh);
    encfc_kernel<<<BT / 8, 256>>>(enc, fc_w);
    pre_gemm_kernel<<<2048, 256>>>(enc, attn_w1, attn_b1);
    decoder_persist<<<NBLK, 256>>>(enc, yhist, attn_w1, attn_w2, w_ih,
                                   fc_w, fc_b, fcf_w, fcf_b, out);
}

// round 15
// speedup vs baseline: 1.6455x; 1.0460x over previous
#include <cuda_runtime.h>
#include <cuda_fp16.h>

#define Bq 512
#define Tq 128
#define Eq 256
#define Dq 256
#define G4 1024
#define BT (Bq*Tq)
#define NBLK 512
#define NLEAF 16
#define PER_LEAF 32   // 512 = 16*32

// ---------------- static device scratch ----------------
__device__ __half g_pre[(size_t)BT * Eq];     // enc @ W1_enc + b1 (fp16, 32MB)
__device__ float g_encfc[BT];                 // enc[b,t,:] . fc_w[0:256]
__device__ float g_whhT[Dq * G4];             // w_hh transposed [k][gate*256+d]
__device__ float g_bsum[G4];
__device__ float g_h[Bq * Dq];
__device__ float g_c[Bq * Dq];
__device__ float g_hp[16 * Bq * Eq];          // 16 K-partials of [h|c]@W1_hc
__device__ float g_gp[4 * (size_t)Bq * G4];   // 4 K-partials of h@w_hhT
__device__ unsigned g_cnt[NLEAF * 32];
__device__ unsigned g_master;
__device__ volatile unsigned g_gen;
__device__ unsigned g_chp, g_cgp;             // monotonic phase counters

struct SmA { float As[16][136]; float Bs[16][68]; };   // prepass engine layout
struct SmStep { float As[16][132]; };                  // step engine: A slab only
struct SmB {
    float hp[256]; unsigned hp2[128]; float sc[128]; float ctxp[8][256];
    float ctx[256]; float red[8]; float misc[4];
};
struct SmAll {
    union { SmStep a; SmB b; SmA pp; } u;
    float Bper[64][68];                                // persistent B tile (<=16KB used)
};

__device__ __forceinline__ unsigned tanh_h2(unsigned x) {
    unsigned y; asm("tanh.approx.f16x2 %0, %1;" : "=r"(y) : "r"(x)); return y;
}
__device__ __forceinline__ float sigmoid_f(float x) {
    return __fdividef(1.0f, 1.0f + __expf(-x));
}

// packed dual-fp32 FMA
#define FMA_X2(acc, a, b) \
    asm("fma.rn.f32x2 %0, %1, %2, %0;" : "+l"(acc) : "l"(a), "l"(b))

__device__ __forceinline__ unsigned long long pack2(float lo, float hi) {
    unsigned long long r;
    asm("mov.b64 %0, {%1, %2};" : "=l"(r) : "f"(lo), "f"(hi));
    return r;
}
__device__ __forceinline__ float2 unpack2(unsigned long long v) {
    float lo, hi;
    asm("mov.b64 {%0, %1}, %2;" : "=f"(lo), "=f"(hi) : "l"(v));
    return make_float2(lo, hi);
}

// ---------------- step GEMM: A staged per slab, B persistent in smem ----------------
__device__ __forceinline__ void step_gemm(SmAll* sm,
        const float* __restrict__ A, int lda,
        float* __restrict__ C, int ldc, int K)
{
    const int tid = threadIdx.x;
    const int ty = tid >> 4, tx = tid & 15;
    const int arow = tid >> 2, ac4 = (tid & 3) << 2;

    unsigned long long acc2[4][4];
#pragma unroll
    for (int p = 0; p < 4; p++)
#pragma unroll
        for (int j = 0; j < 4; j++) acc2[p][j] = 0ull;

    for (int k0 = 0; k0 < K; k0 += 16) {
        float4 av0 = __ldcg((const float4*)(A + (size_t)arow * lda + k0 + ac4));
        float4 av1 = __ldcg((const float4*)(A + (size_t)(arow + 64) * lda + k0 + ac4));
        sm->u.a.As[ac4 + 0][arow] = av0.x; sm->u.a.As[ac4 + 1][arow] = av0.y;
        sm->u.a.As[ac4 + 2][arow] = av0.z; sm->u.a.As[ac4 + 3][arow] = av0.w;
        sm->u.a.As[ac4 + 0][arow + 64] = av1.x; sm->u.a.As[ac4 + 1][arow + 64] = av1.y;
        sm->u.a.As[ac4 + 2][arow + 64] = av1.z; sm->u.a.As[ac4 + 3][arow + 64] = av1.w;
        __syncthreads();
#pragma unroll
        for (int k = 0; k < 16; k++) {
            ulonglong2 aLo = *(const ulonglong2*)&sm->u.a.As[k][ty << 3];
            ulonglong2 aHi = *(const ulonglong2*)&sm->u.a.As[k][(ty << 3) + 4];
            float4 b4 = *(const float4*)&sm->Bper[k0 + k][tx << 2];
            unsigned long long bd0 = pack2(b4.x, b4.x);
            unsigned long long bd1 = pack2(b4.y, b4.y);
            unsigned long long bd2 = pack2(b4.z, b4.z);
            unsigned long long bd3 = pack2(b4.w, b4.w);
            FMA_X2(acc2[0][0], aLo.x, bd0); FMA_X2(acc2[0][1], aLo.x, bd1);
            FMA_X2(acc2[0][2], aLo.x, bd2); FMA_X2(acc2[0][3], aLo.x, bd3);
            FMA_X2(acc2[1][0], aLo.y, bd0); FMA_X2(acc2[1][1], aLo.y, bd1);
            FMA_X2(acc2[1][2], aLo.y, bd2); FMA_X2(acc2[1][3], aLo.y, bd3);
            FMA_X2(acc2[2][0], aHi.x, bd0); FMA_X2(acc2[2][1], aHi.x, bd1);
            FMA_X2(acc2[2][2], aHi.x, bd2); FMA_X2(acc2[2][3], aHi.x, bd3);
            FMA_X2(acc2[3][0], aHi.y, bd0); FMA_X2(acc2[3][1], aHi.y, bd1);
            FMA_X2(acc2[3][2], aHi.y, bd2); FMA_X2(acc2[3][3], aHi.y, bd3);
        }
        __syncthreads();
    }

#pragma unroll
    for (int p = 0; p < 4; p++) {
        float2 v0 = unpack2(acc2[p][0]);
        float2 v1 = unpack2(acc2[p][1]);
        float2 v2 = unpack2(acc2[p][2]);
        float2 v3 = unpack2(acc2[p][3]);
        size_t off0 = (size_t)((ty << 3) + 2 * p) * ldc + (tx << 2);
        size_t off1 = off0 + ldc;
        *(float4*)(C + off0) = make_float4(v0.x, v1.x, v2.x, v3.x);
        *(float4*)(C + off1) = make_float4(v0.y, v1.y, v2.y, v3.y);
    }
}

// ---------------- prepass GEMM (R11 engine, unchanged) ----------------
template<typename TO>
__device__ __forceinline__ void gemm128x64(SmA* s,
        const float* __restrict__ A, int lda,
        const float* __restrict__ Bm, int ldb,
        TO* __restrict__ C, int ldc, int K,
        const float* __restrict__ bias)
{
    const int tid = threadIdx.x;
    const int ty = tid >> 4, tx = tid & 15;
    const int arow = tid >> 2, ac4 = (tid & 3) << 2;
    const int bk = tid >> 4, bc4 = (tid & 15) << 2;

    unsigned long long acc2[4][4];
#pragma unroll
    for (int p = 0; p < 4; p++)
#pragma unroll
        for (int j = 0; j < 4; j++) acc2[p][j] = 0ull;

    for (int k0 = 0; k0 < K; k0 += 16) {
        float4 av0 = __ldcg((const float4*)(A + (size_t)arow * lda + k0 + ac4));
        float4 av1 = __ldcg((const float4*)(A + (size_t)(arow + 64) * lda + k0 + ac4));
        float4 bv  = __ldg((const float4*)(Bm + (size_t)(k0 + bk) * ldb + bc4));
        s->As[ac4 + 0][arow] = av0.x; s->As[ac4 + 1][arow] = av0.y;
        s->As[ac4 + 2][arow] = av0.z; s->As[ac4 + 3][arow] = av0.w;
        s->As[ac4 + 0][arow + 64] = av1.x; s->As[ac4 + 1][arow + 64] = av1.y;
        s->As[ac4 + 2][arow + 64] = av1.z; s->As[ac4 + 3][arow + 64] = av1.w;
        *(float4*)&s->Bs[bk][bc4] = bv;
        __syncthreads();
#pragma unroll
        for (int k = 0; k < 16; k++) {
            const float2* ap = (const float2*)&s->As[k][ty << 3];
            float4 b4 = *(const float4*)&s->Bs[k][tx << 2];
            unsigned long long bd0 = pack2(b4.x, b4.x);
            unsigned long long bd1 = pack2(b4.y, b4.y);
            unsigned long long bd2 = pack2(b4.z, b4.z);
            unsigned long long bd3 = pack2(b4.w, b4.w);
#pragma unroll
            for (int p = 0; p < 4; p++) {
                float2 a2 = ap[p];
                unsigned long long av = pack2(a2.x, a2.y);
                FMA_X2(acc2[p][0], av, bd0);
                FMA_X2(acc2[p][1], av, bd1);
                FMA_X2(acc2[p][2], av, bd2);
                FMA_X2(acc2[p][3], av, bd3);
            }
        }
        __syncthreads();
    }
#pragma unroll
    for (int p = 0; p < 4; p++) {
        float2 v0 = unpack2(acc2[p][0]);
        float2 v1 = unpack2(acc2[p][1]);
        float2 v2 = unpack2(acc2[p][2]);
        float2 v3 = unpack2(acc2[p][3]);
        float r0[4] = {v0.x, v1.x, v2.x, v3.x};
        float r1[4] = {v0.y, v1.y, v2.y, v3.y};
        if (bias) {
#pragma unroll
            for (int j = 0; j < 4; j++) {
                float bj = bias[(tx << 2) + j];
                r0[j] += bj; r1[j] += bj;
            }
        }
        size_t off0 = (size_t)((ty << 3) + 2 * p) * ldc + (tx << 2);
        size_t off1 = off0 + ldc;
        if constexpr (sizeof(TO) == 2) {
            __half2 h00 = __floats2half2_rn(r0[0], r0[1]);
            __half2 h01 = __floats2half2_rn(r0[2], r0[3]);
            __half2 h10 = __floats2half2_rn(r1[0], r1[1]);
            __half2 h11 = __floats2half2_rn(r1[2], r1[3]);
            uint2 u0; u0.x = *(unsigned*)&h00; u0.y = *(unsigned*)&h01;
            uint2 u1; u1.x = *(unsigned*)&h10; u1.y = *(unsigned*)&h11;
            *(uint2*)((__half*)C + off0) = u0;
            *(uint2*)((__half*)C + off1) = u1;
        } else {
            *(float4*)((float*)C + off0) = make_float4(r0[0], r0[1], r0[2], r0[3]);
            *(float4*)((float*)C + off1) = make_float4(r1[0], r1[1], r1[2], r1[3]);
        }
    }
    __syncthreads();
}

// ---- release: all stores visible, then one arrival per block ----
__device__ __forceinline__ void post_count(unsigned* c) {
    __threadfence();
    __syncthreads();
    if (threadIdx.x == 0) atomicAdd(c, 1u);
}
// ---- acquire: spin until target arrivals, then fence ----
__device__ __forceinline__ void wait_count(unsigned* c, unsigned target) {
    if (threadIdx.x == 0) {
        while (*(volatile unsigned*)c < target) __nanosleep(32);
    }
    __syncthreads();
    __threadfence();
}

__device__ __forceinline__ void gridbar() {
    __threadfence();
    __syncthreads();
    if (threadIdx.x == 0) {
        unsigned gen = g_gen;
        unsigned leaf = (blockIdx.x & (NLEAF - 1)) * 32;
        unsigned v = atomicAdd(&g_cnt[leaf], 1u) + 1u;
        if (v == (gen + 1u) * PER_LEAF) {
            unsigned m = atomicAdd(&g_master, 1u) + 1u;
            if (m == (gen + 1u) * NLEAF) {
                __threadfence();
                g_gen = gen + 1u;
            } else {
                while (g_gen == gen) __nanosleep(32);
            }
        } else {
            while (g_gen == gen) __nanosleep(64);
        }
        __threadfence();
    }
    __syncthreads();
}

__global__ void __launch_bounds__(256, 4) decoder_persist(
        const float* __restrict__ enc, const float* __restrict__ yhist,
        const float* __restrict__ attn_w1, const float* __restrict__ attn_w2,
        const float* __restrict__ w_ih,
        const float* __restrict__ fc_w, const float* __restrict__ fc_b,
        const float* __restrict__ fcf_w, const float* __restrict__ fcf_b,
        float* __restrict__ out)
{
    __shared__ SmAll sm;
    const int bid = blockIdx.x;
    const int tid = threadIdx.x;
    const int lane = tid & 31, warp = tid >> 5;
    const int b = bid;
    const bool is_gp = (bid < 256);

    // ---- unit geometry + persistent B tile load (once) ----
    const float* Abase; int lda; float* Cbase; int ldc; int Kdim;
    {
        const float* Bm; int ldb; int Krows;
        if (is_gp) {
            int kq = bid & 3, tile = bid >> 2;
            int mt = tile >> 4, nt = tile & 15;
            Abase = g_h + (size_t)mt * 128 * Dq + kq * 64; lda = Dq;
            Bm = g_whhT + (size_t)(kq * 64) * G4 + nt * 64; ldb = G4; Krows = 64;
            Cbase = g_gp + (size_t)kq * (Bq * G4) + (size_t)mt * 128 * G4 + nt * 64;
            ldc = G4; Kdim = 64;
        } else {
            int u = bid - 256;
            int tile = u >> 4, kq = u & 15;
            int mt = tile >> 2, nt = tile & 3;
            Abase = (kq < 8 ? g_h + kq * 32 : g_c + (kq - 8) * 32)
                    + (size_t)mt * 128 * Dq; lda = Dq;
            Bm = attn_w1 + (size_t)(kq * 32) * Eq + nt * 64; ldb = Eq; Krows = 32;
            Cbase = g_hp + (size_t)kq * (Bq * Eq) + (size_t)mt * 128 * Eq + nt * 64;
            ldc = Eq; Kdim = 32;
        }
        for (int i = tid; i < Krows * 16; i += 256) {
            int kk = i >> 4, c4 = (i & 15) << 2;
            *(float4*)&sm.Bper[kk][c4] = __ldg((const float4*)(Bm + (size_t)kk * ldb + c4));
        }
        __syncthreads();
    }

    for (int t = 0; t < Tq; t++) {
        const unsigned tgt = 256u * (unsigned)(t + 1);

        // ============ phase 1: my GEMM partial, then split arrival ============
        step_gemm(&sm, Abase, lda, Cbase, ldc, Kdim);
        post_count(is_gp ? &g_cgp : &g_chp);

        // ============ attention needs hp only ============
        wait_count(&g_chp, tgt);
        {
            float hpv = 0.f;
#pragma unroll
            for (int q = 0; q < 16; q++)
                hpv += __ldcg(&g_hp[(size_t)q * (Bq * Eq) + b * Eq + tid]);
            sm.u.b.hp[tid] = hpv;
            __syncthreads();
            if (tid < 128) {
                __half2 h2 = __floats2half2_rn(sm.u.b.hp[2 * tid], sm.u.b.hp[2 * tid + 1]);
                sm.u.b.hp2[tid] = *(unsigned*)&h2;
            }
            __syncthreads();

            unsigned hp2r[4];
            float w2r[8];
#pragma unroll
            for (int q = 0; q < 4; q++) hp2r[q] = sm.u.b.hp2[lane * 4 + q];
#pragma unroll
            for (int j = 0; j < 8; j++) w2r[j] = __ldg(&attn_w2[lane * 8 + j]);

            // scores: 8 warps x 16 t's, 4 loads in flight; tanh in f16x2
            const uint4* preb = (const uint4*)(g_pre + (size_t)b * Tq * Eq);
#pragma unroll
            for (int tb = 0; tb < 4; tb++) {
                int tt0 = warp + tb * 32;
                uint4 pv[4];
#pragma unroll
                for (int j = 0; j < 4; j++)
                    pv[j] = __ldg(preb + (size_t)(tt0 + j * 8) * 32 + lane);
#pragma unroll
                for (int j = 0; j < 4; j++) {
                    const unsigned* ph = (const unsigned*)&pv[j];
                    float a = 0.f;
#pragma unroll
                    for (int q = 0; q < 4; q++) {
                        __half2 x = *(const __half2*)&ph[q] + *(const __half2*)&hp2r[q];
                        unsigned th = tanh_h2(*(unsigned*)&x);
                        float2 f = __half22float2(*(const __half2*)&th);
                        a = fmaf(w2r[2 * q], f.x, a);
                        a = fmaf(w2r[2 * q + 1], f.y, a);
                    }
#pragma unroll
                    for (int o = 16; o; o >>= 1) a += __shfl_xor_sync(0xffffffffu, a, o);
                    if (lane == 0) sm.u.b.sc[tt0 + j * 8] = a;
                }
            }
            __syncthreads();

            // softmax over T=128 (attn_b2 dropped: shift-invariant)
            float sv = (tid < Tq) ? sm.u.b.sc[tid] : -3.0e38f;
            float m = sv;
#pragma unroll
            for (int o = 16; o; o >>= 1) m = fmaxf(m, __shfl_xor_sync(0xffffffffu, m, o));
            if (lane == 0) sm.u.b.red[warp] = m;
            __syncthreads();
            if (tid == 0) {
                float mm = sm.u.b.red[0];
#pragma unroll
                for (int w = 1; w < 8; w++) mm = fmaxf(mm, sm.u.b.red[w]);
                sm.u.b.misc[0] = mm;
            }
            __syncthreads();
            float ex = (tid < Tq) ? __expf(sv - sm.u.b.misc[0]) : 0.f;
            float ss = ex;
#pragma unroll
            for (int o = 16; o; o >>= 1) ss += __shfl_xor_sync(0xffffffffu, ss, o);
            if (lane == 0) sm.u.b.red[warp] = ss;
            __syncthreads();
            if (tid == 0) {
                float tot = 0.f;
#pragma unroll
                for (int w = 0; w < 8; w++) tot += sm.u.b.red[w];
                sm.u.b.misc[1] = __fdividef(1.0f, tot);
            }
            if (tid < Tq) sm.u.b.sc[tid] = ex;
            __syncthreads();
            float invs = sm.u.b.misc[1];

            // y_dot = sum_t ex[t] * encfc[b,t]
            float yd = (tid < Tq) ? sm.u.b.sc[tid] * __ldg(&g_encfc[b * Tq + tid]) : 0.f;
#pragma unroll
            for (int o = 16; o; o >>= 1) yd += __shfl_xor_sync(0xffffffffu, yd, o);
            if (lane == 0) sm.u.b.red[warp] = yd;
            __syncthreads();
            if (tid == 0) {
                float tot = 0.f;
#pragma unroll
                for (int w = 0; w < 8; w++) tot += sm.u.b.red[w];
                sm.u.b.misc[2] = tot * invs + __ldg(&yhist[b * Tq + t]) * fc_w[256] + fc_b[0];
            }

            // full ctx only at the final step (for fc_final)
            if (t == Tq - 1) {
                float a8[8] = {0.f, 0.f, 0.f, 0.f, 0.f, 0.f, 0.f, 0.f};
                const float4* encb = (const float4*)(enc + (size_t)b * Tq * Eq);
#pragma unroll 2
                for (int i = 0; i < 16; i++) {
                    int tt = (warp << 4) + i;
                    float wgt = sm.u.b.sc[tt];
                    float4 e0 = __ldg(encb + (size_t)tt * 64 + lane * 2);
                    float4 e1 = __ldg(encb + (size_t)tt * 64 + lane * 2 + 1);
                    a8[0] = fmaf(wgt, e0.x, a8[0]); a8[1] = fmaf(wgt, e0.y, a8[1]);
                    a8[2] = fmaf(wgt, e0.z, a8[2]); a8[3] = fmaf(wgt, e0.w, a8[3]);
                    a8[4] = fmaf(wgt, e1.x, a8[4]); a8[5] = fmaf(wgt, e1.y, a8[5]);
                    a8[6] = fmaf(wgt, e1.z, a8[6]); a8[7] = fmaf(wgt, e1.w, a8[7]);
                }
                __syncthreads();
#pragma unroll
                for (int j = 0; j < 8; j++) sm.u.b.ctxp[warp][lane * 8 + j] = a8[j];
                __syncthreads();
                float cv = 0.f;
#pragma unroll
                for (int w = 0; w < 8; w++) cv += sm.u.b.ctxp[w][tid];
                sm.u.b.ctx[tid] = cv * invs;
            }
            __syncthreads();

            // ============ epilogue needs gp ============
            wait_count(&g_cgp, tgt);

            // LSTM epilogue (thread = d)
            float yt = sm.u.b.misc[2];
            int d = tid;
            float gv[4];
#pragma unroll
            for (int g = 0; g < 4; g++) {
                float a = fmaf(yt, __ldg(&w_ih[g * 256 + d]), g_bsum[g * 256 + d]);
#pragma unroll
                for (int kq = 0; kq < 4; kq++)
                    a += __ldcg(&g_gp[(size_t)kq * (Bq * G4) + (size_t)b * G4 + g * 256 + d]);
                gv[g] = a;
            }
            float cprev = __ldcg(&g_c[b * Dq + d]);
            float cn = sigmoid_f(gv[1]) * cprev + sigmoid_f(gv[0]) * tanhf(gv[2]);
            float hn = sigmoid_f(gv[3]) * tanhf(cn);
            g_c[b * Dq + d] = cn;
            g_h[b * Dq + d] = hn;

            if (t == Tq - 1) {
                float q = hn * __ldg(&fcf_w[d]) + sm.u.b.ctx[d] * __ldg(&fcf_w[Dq + d]);
#pragma unroll
                for (int o = 16; o; o >>= 1) q += __shfl_xor_sync(0xffffffffu, q, o);
                __syncthreads();
                if (lane == 0) sm.u.b.red[warp] = q;
                __syncthreads();
                if (tid == 0) {
                    float tot = 0.f;
#pragma unroll
                    for (int w = 0; w < 8; w++) tot += sm.u.b.red[w];
                    out[b] = tot + fcf_b[0];
                }
            }
        }
        // ============ full barrier: h,c updated before next step's GEMM ============
        gridbar();
    }
}

__global__ void prep_kernel(const float* __restrict__ w_hh,
                            const float* __restrict__ b_ih,
                            const float* __restrict__ b_hh)
{
    int i = blockIdx.x * blockDim.x + threadIdx.x;
    if (i < G4 * Dq) {
        int j = i >> 8, k = i & 255;
        g_whhT[(size_t)k * G4 + j] = w_hh[i];
    }
    if (i < G4) g_bsum[i] = b_ih[i] + b_hh[i];
    if (i < Bq * Dq) { g_h[i] = 0.f; g_c[i] = 0.f; }
    if (i < NLEAF * 32) g_cnt[i] = 0u;
    if (i == 0) { g_master = 0u; g_gen = 0u; g_chp = 0u; g_cgp = 0u; }
}

// encfc[b,t] = enc[b,t,:] . fc_w[0:256]   (one warp per (b,t))
__global__ void __launch_bounds__(256) encfc_kernel(
        const float* __restrict__ enc, const float* __restrict__ fc_w)
{
    int w = blockIdx.x * 8 + (threadIdx.x >> 5);
    int lane = threadIdx.x & 31;
    const float4* p = (const float4*)(enc + (size_t)w * Eq);
    const float4* q = (const float4*)fc_w;
    float s = 0.f;
#pragma unroll
    for (int j = 0; j < 2; j++) {
        float4 e = __ldcg(p + lane + 32 * j);
        float4 f = __ldg(q + lane + 32 * j);
        s += e.x * f.x + e.y * f.y + e.z * f.z + e.w * f.w;
    }
#pragma unroll
    for (int o = 16; o; o >>= 1) s += __shfl_xor_sync(0xffffffffu, s, o);
    if (lane == 0) g_encfc[w] = s;
}

__global__ void __launch_bounds__(256) pre_gemm_kernel(
        const float* __restrict__ enc, const float* __restrict__ attn_w1,
        const float* __restrict__ attn_b1)
{
    __shared__ SmA sa;
    int mt = blockIdx.x >> 2, nt = blockIdx.x & 3;
    gemm128x64<__half>(&sa,
        enc + (size_t)mt * 128 * Eq, Eq,
        attn_w1 + (size_t)(2 * Dq) * Eq + nt * 64, Eq,
        g_pre + (size_t)mt * 128 * Eq + nt * 64, Eq, 256,
        attn_b1 + nt * 64);
}

extern "C" void kernel_launch(void* const* d_in, const int* in_sizes, int n_in,
                              void* d_out, int out_size)
{
    const float* enc     = (const float*)d_in[0];
    const float* yhist   = (const float*)d_in[1];
    const float* attn_w1 = (const float*)d_in[2];
    const float* attn_b1 = (const float*)d_in[3];
    const float* attn_w2 = (const float*)d_in[4];
    // d_in[5] = attn_b2: unused (softmax is shift-invariant)
    const float* w_ih    = (const float*)d_in[6];
    const float* w_hh    = (const float*)d_in[7];
    const float* b_ih    = (const float*)d_in[8];
    const float* b_hh    = (const float*)d_in[9];
    const float* fc_w    = (const float*)d_in[10];
    const float* fc_b    = (const float*)d_in[11];
    const float* fcf_w   = (const float*)d_in[12];
    const float* fcf_b   = (const float*)d_in[13];
    float* out = (float*)d_out;

    prep_kernel<<<1024, 256>>>(w_hh, b_ih, b_hh);
    encfc_kernel<<<BT / 8, 256>>>(enc, fc_w);
    pre_gemm_kernel<<<2048, 256>>>(enc, attn_w1, attn_b1);
    decoder_persist<<<NBLK, 256>>>(enc, yhist, attn_w1, attn_w2, w_ih,
                                   fc_w, fc_b, fcf_w, fcf_b, out);
}

// round 16
// speedup vs baseline: 1.8220x; 1.1072x over previous
#include <cuda_runtime.h>
#include <cuda_fp16.h>

#define Bq 512
#define Tq 128
#define Eq 256
#define Dq 256
#define G4 1024
#define BT (Bq*Tq)
#define NBLK 512

// ---------------- static device scratch ----------------
__device__ __half g_pre[(size_t)BT * Eq];     // enc @ W1_enc + b1 (fp16, 32MB)
__device__ float g_encfc[BT];                 // enc[b,t,:] . fc_w[0:256]
__device__ float g_whhT[Dq * G4];             // w_hh transposed [k][gate*256+d]
__device__ float g_bsum[G4];
__device__ float g_h[Bq * Dq];
__device__ float g_c[Bq * Dq];
__device__ float g_hp[16 * Bq * Eq];          // 16 K-partials of [h|c]@W1_hc
__device__ float g_gp[4 * (size_t)Bq * G4];   // 4 K-partials of h@w_hhT
__device__ unsigned g_chp, g_cgp;             // monotonic phase counters
__device__ unsigned g_cep[4 * 32];            // per-row-group epilogue counters (128B apart)

struct SmA { float As[16][136]; float Bs[16][68]; };   // prepass engine layout
struct SmStep { float As[16][132]; };                  // step engine: A slab only
struct SmB {
    float hp[256]; unsigned hp2[128]; float sc[128]; float ctxp[8][256];
    float ctx[256]; float red[8]; float misc[4];
};
struct SmAll {
    union { SmStep a; SmB b; SmA pp; } u;
    float Bper[64][68];                                // persistent B tile (<=16KB used)
};

__device__ __forceinline__ unsigned tanh_h2(unsigned x) {
    unsigned y; asm("tanh.approx.f16x2 %0, %1;" : "=r"(y) : "r"(x)); return y;
}
__device__ __forceinline__ float sigmoid_f(float x) {
    return __fdividef(1.0f, 1.0f + __expf(-x));
}

// packed dual-fp32 FMA
#define FMA_X2(acc, a, b) \
    asm("fma.rn.f32x2 %0, %1, %2, %0;" : "+l"(acc) : "l"(a), "l"(b))

__device__ __forceinline__ unsigned long long pack2(float lo, float hi) {
    unsigned long long r;
    asm("mov.b64 %0, {%1, %2};" : "=l"(r) : "f"(lo), "f"(hi));
    return r;
}
__device__ __forceinline__ float2 unpack2(unsigned long long v) {
    float lo, hi;
    asm("mov.b64 {%0, %1}, %2;" : "=f"(lo), "=f"(hi) : "l"(v));
    return make_float2(lo, hi);
}

// ---------------- step GEMM: A staged per slab, B persistent in smem ----------------
__device__ __forceinline__ void step_gemm(SmAll* sm,
        const float* __restrict__ A, int lda,
        float* __restrict__ C, int ldc, int K)
{
    const int tid = threadIdx.x;
    const int ty = tid >> 4, tx = tid & 15;
    const int arow = tid >> 2, ac4 = (tid & 3) << 2;

    unsigned long long acc2[4][4];
#pragma unroll
    for (int p = 0; p < 4; p++)
#pragma unroll
        for (int j = 0; j < 4; j++) acc2[p][j] = 0ull;

    for (int k0 = 0; k0 < K; k0 += 16) {
        float4 av0 = __ldcg((const float4*)(A + (size_t)arow * lda + k0 + ac4));
        float4 av1 = __ldcg((const float4*)(A + (size_t)(arow + 64) * lda + k0 + ac4));
        sm->u.a.As[ac4 + 0][arow] = av0.x; sm->u.a.As[ac4 + 1][arow] = av0.y;
        sm->u.a.As[ac4 + 2][arow] = av0.z; sm->u.a.As[ac4 + 3][arow] = av0.w;
        sm->u.a.As[ac4 + 0][arow + 64] = av1.x; sm->u.a.As[ac4 + 1][arow + 64] = av1.y;
        sm->u.a.As[ac4 + 2][arow + 64] = av1.z; sm->u.a.As[ac4 + 3][arow + 64] = av1.w;
        __syncthreads();
#pragma unroll
        for (int k = 0; k < 16; k++) {
            ulonglong2 aLo = *(const ulonglong2*)&sm->u.a.As[k][ty << 3];
            ulonglong2 aHi = *(const ulonglong2*)&sm->u.a.As[k][(ty << 3) + 4];
            float4 b4 = *(const float4*)&sm->Bper[k0 + k][tx << 2];
            unsigned long long bd0 = pack2(b4.x, b4.x);
            unsigned long long bd1 = pack2(b4.y, b4.y);
            unsigned long long bd2 = pack2(b4.z, b4.z);
            unsigned long long bd3 = pack2(b4.w, b4.w);
            FMA_X2(acc2[0][0], aLo.x, bd0); FMA_X2(acc2[0][1], aLo.x, bd1);
            FMA_X2(acc2[0][2], aLo.x, bd2); FMA_X2(acc2[0][3], aLo.x, bd3);
            FMA_X2(acc2[1][0], aLo.y, bd0); FMA_X2(acc2[1][1], aLo.y, bd1);
            FMA_X2(acc2[1][2], aLo.y, bd2); FMA_X2(acc2[1][3], aLo.y, bd3);
            FMA_X2(acc2[2][0], aHi.x, bd0); FMA_X2(acc2[2][1], aHi.x, bd1);
            FMA_X2(acc2[2][2], aHi.x, bd2); FMA_X2(acc2[2][3], aHi.x, bd3);
            FMA_X2(acc2[3][0], aHi.y, bd0); FMA_X2(acc2[3][1], aHi.y, bd1);
            FMA_X2(acc2[3][2], aHi.y, bd2); FMA_X2(acc2[3][3], aHi.y, bd3);
        }
        __syncthreads();
    }

#pragma unroll
    for (int p = 0; p < 4; p++) {
        float2 v0 = unpack2(acc2[p][0]);
        float2 v1 = unpack2(acc2[p][1]);
        float2 v2 = unpack2(acc2[p][2]);
        float2 v3 = unpack2(acc2[p][3]);
        size_t off0 = (size_t)((ty << 3) + 2 * p) * ldc + (tx << 2);
        size_t off1 = off0 + ldc;
        *(float4*)(C + off0) = make_float4(v0.x, v1.x, v2.x, v3.x);
        *(float4*)(C + off1) = make_float4(v0.y, v1.y, v2.y, v3.y);
    }
}

// ---------------- prepass GEMM (R11 engine, unchanged) ----------------
template<typename TO>
__device__ __forceinline__ void gemm128x64(SmA* s,
        const float* __restrict__ A, int lda,
        const float* __restrict__ Bm, int ldb,
        TO* __restrict__ C, int ldc, int K,
        const float* __restrict__ bias)
{
    const int tid = threadIdx.x;
    const int ty = tid >> 4, tx = tid & 15;
    const int arow = tid >> 2, ac4 = (tid & 3) << 2;
    const int bk = tid >> 4, bc4 = (tid & 15) << 2;

    unsigned long long acc2[4][4];
#pragma unroll
    for (int p = 0; p < 4; p++)
#pragma unroll
        for (int j = 0; j < 4; j++) acc2[p][j] = 0ull;

    for (int k0 = 0; k0 < K; k0 += 16) {
        float4 av0 = __ldcg((const float4*)(A + (size_t)arow * lda + k0 + ac4));
        float4 av1 = __ldcg((const float4*)(A + (size_t)(arow + 64) * lda + k0 + ac4));
        float4 bv  = __ldg((const float4*)(Bm + (size_t)(k0 + bk) * ldb + bc4));
        s->As[ac4 + 0][arow] = av0.x; s->As[ac4 + 1][arow] = av0.y;
        s->As[ac4 + 2][arow] = av0.z; s->As[ac4 + 3][arow] = av0.w;
        s->As[ac4 + 0][arow + 64] = av1.x; s->As[ac4 + 1][arow + 64] = av1.y;
        s->As[ac4 + 2][arow + 64] = av1.z; s->As[ac4 + 3][arow + 64] = av1.w;
        *(float4*)&s->Bs[bk][bc4] = bv;
        __syncthreads();
#pragma unroll
        for (int k = 0; k < 16; k++) {
            const float2* ap = (const float2*)&s->As[k][ty << 3];
            float4 b4 = *(const float4*)&s->Bs[k][tx << 2];
            unsigned long long bd0 = pack2(b4.x, b4.x);
            unsigned long long bd1 = pack2(b4.y, b4.y);
            unsigned long long bd2 = pack2(b4.z, b4.z);
            unsigned long long bd3 = pack2(b4.w, b4.w);
#pragma unroll
            for (int p = 0; p < 4; p++) {
                float2 a2 = ap[p];
                unsigned long long av = pack2(a2.x, a2.y);
                FMA_X2(acc2[p][0], av, bd0);
                FMA_X2(acc2[p][1], av, bd1);
                FMA_X2(acc2[p][2], av, bd2);
                FMA_X2(acc2[p][3], av, bd3);
            }
        }
        __syncthreads();
    }
#pragma unroll
    for (int p = 0; p < 4; p++) {
        float2 v0 = unpack2(acc2[p][0]);
        float2 v1 = unpack2(acc2[p][1]);
        float2 v2 = unpack2(acc2[p][2]);
        float2 v3 = unpack2(acc2[p][3]);
        float r0[4] = {v0.x, v1.x, v2.x, v3.x};
        float r1[4] = {v0.y, v1.y, v2.y, v3.y};
        if (bias) {
#pragma unroll
            for (int j = 0; j < 4; j++) {
                float bj = bias[(tx << 2) + j];
                r0[j] += bj; r1[j] += bj;
            }
        }
        size_t off0 = (size_t)((ty << 3) + 2 * p) * ldc + (tx << 2);
        size_t off1 = off0 + ldc;
        if constexpr (sizeof(TO) == 2) {
            __half2 h00 = __floats2half2_rn(r0[0], r0[1]);
            __half2 h01 = __floats2half2_rn(r0[2], r0[3]);
            __half2 h10 = __floats2half2_rn(r1[0], r1[1]);
            __half2 h11 = __floats2half2_rn(r1[2], r1[3]);
            uint2 u0; u0.x = *(unsigned*)&h00; u0.y = *(unsigned*)&h01;
            uint2 u1; u1.x = *(unsigned*)&h10; u1.y = *(unsigned*)&h11;
            *(uint2*)((__half*)C + off0) = u0;
            *(uint2*)((__half*)C + off1) = u1;
        } else {
            *(float4*)((float*)C + off0) = make_float4(r0[0], r0[1], r0[2], r0[3]);
            *(float4*)((float*)C + off1) = make_float4(r1[0], r1[1], r1[2], r1[3]);
        }
    }
    __syncthreads();
}

// ---- release: all stores visible, then one arrival per block ----
__device__ __forceinline__ void post_count(unsigned* c) {
    __threadfence();
    __syncthreads();
    if (threadIdx.x == 0) atomicAdd(c, 1u);
}
// ---- acquire: spin until target arrivals, then fence ----
__device__ __forceinline__ void wait_count(unsigned* c, unsigned target) {
    if (threadIdx.x == 0) {
        while (*(volatile unsigned*)c < target) __nanosleep(32);
    }
    __syncthreads();
    __threadfence();
}

__global__ void __launch_bounds__(256, 4) decoder_persist(
        const float* __restrict__ enc, const float* __restrict__ yhist,
        const float* __restrict__ attn_w1, const float* __restrict__ attn_w2,
        const float* __restrict__ w_ih,
        const float* __restrict__ fc_w, const float* __restrict__ fc_b,
        const float* __restrict__ fcf_w, const float* __restrict__ fcf_b,
        float* __restrict__ out)
{
    __shared__ SmAll sm;
    const int bid = blockIdx.x;
    const int tid = threadIdx.x;
    const int lane = tid & 31, warp = tid >> 5;
    const int b = bid;
    const bool is_gp = (bid < 256);

    // ---- unit geometry + persistent B tile load (once) ----
    const float* Abase; int lda; float* Cbase; int ldc; int Kdim; int amt;
    {
        const float* Bm; int ldb; int Krows;
        if (is_gp) {
            int kq = bid & 3, tile = bid >> 2;
            int mt = tile >> 4, nt = tile & 15;
            amt = mt;
            Abase = g_h + (size_t)mt * 128 * Dq + kq * 64; lda = Dq;
            Bm = g_whhT + (size_t)(kq * 64) * G4 + nt * 64; ldb = G4; Krows = 64;
            Cbase = g_gp + (size_t)kq * (Bq * G4) + (size_t)mt * 128 * G4 + nt * 64;
            ldc = G4; Kdim = 64;
        } else {
            int u = bid - 256;
            int tile = u >> 4, kq = u & 15;
            int mt = tile >> 2, nt = tile & 3;
            amt = mt;
            Abase = (kq < 8 ? g_h + kq * 32 : g_c + (kq - 8) * 32)
                    + (size_t)mt * 128 * Dq; lda = Dq;
            Bm = attn_w1 + (size_t)(kq * 32) * Eq + nt * 64; ldb = Eq; Krows = 32;
            Cbase = g_hp + (size_t)kq * (Bq * Eq) + (size_t)mt * 128 * Eq + nt * 64;
            ldc = Eq; Kdim = 32;
        }
        for (int i = tid; i < Krows * 16; i += 256) {
            int kk = i >> 4, c4 = (i & 15) << 2;
            *(float4*)&sm.Bper[kk][c4] = __ldg((const float4*)(Bm + (size_t)kk * ldb + c4));
        }
        __syncthreads();
    }
    unsigned* my_ep_wait = &g_cep[amt * 32];
    unsigned* my_ep_post = &g_cep[(b >> 7) * 32];

    for (int t = 0; t < Tq; t++) {
        const unsigned tgt = 256u * (unsigned)(t + 1);

        // ---- wait: my A-rows' h,c from step t-1 are written ----
        wait_count(my_ep_wait, 128u * (unsigned)t);

        // ============ phase 1: my GEMM partial, then split arrival ============
        step_gemm(&sm, Abase, lda, Cbase, ldc, Kdim);
        post_count(is_gp ? &g_cgp : &g_chp);

        // ============ attention needs hp only ============
        wait_count(&g_chp, tgt);
        {
            float hpv = 0.f;
#pragma unroll
            for (int q = 0; q < 16; q++)
                hpv += __ldcg(&g_hp[(size_t)q * (Bq * Eq) + b * Eq + tid]);
            sm.u.b.hp[tid] = hpv;
            __syncthreads();
            if (tid < 128) {
                __half2 h2 = __floats2half2_rn(sm.u.b.hp[2 * tid], sm.u.b.hp[2 * tid + 1]);
                sm.u.b.hp2[tid] = *(unsigned*)&h2;
            }
            __syncthreads();

            unsigned hp2r[4];
            float w2r[8];
#pragma unroll
            for (int q = 0; q < 4; q++) hp2r[q] = sm.u.b.hp2[lane * 4 + q];
#pragma unroll
            for (int j = 0; j < 8; j++) w2r[j] = __ldg(&attn_w2[lane * 8 + j]);

            // scores: 8 warps x 16 t's, 4 loads in flight; tanh in f16x2
            const uint4* preb = (const uint4*)(g_pre + (size_t)b * Tq * Eq);
#pragma unroll
            for (int tb = 0; tb < 4; tb++) {
                int tt0 = warp + tb * 32;
                uint4 pv[4];
#pragma unroll
                for (int j = 0; j < 4; j++)
                    pv[j] = __ldg(preb + (size_t)(tt0 + j * 8) * 32 + lane);
#pragma unroll
                for (int j = 0; j < 4; j++) {
                    const unsigned* ph = (const unsigned*)&pv[j];
                    float a = 0.f;
#pragma unroll
                    for (int q = 0; q < 4; q++) {
                        __half2 x = *(const __half2*)&ph[q] + *(const __half2*)&hp2r[q];
                        unsigned th = tanh_h2(*(unsigned*)&x);
                        float2 f = __half22float2(*(const __half2*)&th);
                        a = fmaf(w2r[2 * q], f.x, a);
                        a = fmaf(w2r[2 * q + 1], f.y, a);
                    }
#pragma unroll
                    for (int o = 16; o; o >>= 1) a += __shfl_xor_sync(0xffffffffu, a, o);
                    if (lane == 0) sm.u.b.sc[tt0 + j * 8] = a;
                }
            }
            __syncthreads();

            // softmax over T=128 (attn_b2 dropped: shift-invariant)
            float sv = (tid < Tq) ? sm.u.b.sc[tid] : -3.0e38f;
            float m = sv;
#pragma unroll
            for (int o = 16; o; o >>= 1) m = fmaxf(m, __shfl_xor_sync(0xffffffffu, m, o));
            if (lane == 0) sm.u.b.red[warp] = m;
            __syncthreads();
            if (tid == 0) {
                float mm = sm.u.b.red[0];
#pragma unroll
                for (int w = 1; w < 8; w++) mm = fmaxf(mm, sm.u.b.red[w]);
                sm.u.b.misc[0] = mm;
            }
            __syncthreads();
            float ex = (tid < Tq) ? __expf(sv - sm.u.b.misc[0]) : 0.f;
            float ss = ex;
#pragma unroll
            for (int o = 16; o; o >>= 1) ss += __shfl_xor_sync(0xffffffffu, ss, o);
            if (lane == 0) sm.u.b.red[warp] = ss;
            __syncthreads();
            if (tid == 0) {
                float tot = 0.f;
#pragma unroll
                for (int w = 0; w < 8; w++) tot += sm.u.b.red[w];
                sm.u.b.misc[1] = __fdividef(1.0f, tot);
            }
            if (tid < Tq) sm.u.b.sc[tid] = ex;
            __syncthreads();
            float invs = sm.u.b.misc[1];

            // y_dot = sum_t ex[t] * encfc[b,t]
            float yd = (tid < Tq) ? sm.u.b.sc[tid] * __ldg(&g_encfc[b * Tq + tid]) : 0.f;
#pragma unroll
            for (int o = 16; o; o >>= 1) yd += __shfl_xor_sync(0xffffffffu, yd, o);
            if (lane == 0) sm.u.b.red[warp] = yd;
            __syncthreads();
            if (tid == 0) {
                float tot = 0.f;
#pragma unroll
                for (int w = 0; w < 8; w++) tot += sm.u.b.red[w];
                sm.u.b.misc[2] = tot * invs + __ldg(&yhist[b * Tq + t]) * fc_w[256] + fc_b[0];
            }

            // full ctx only at the final step (for fc_final)
            if (t == Tq - 1) {
                float a8[8] = {0.f, 0.f, 0.f, 0.f, 0.f, 0.f, 0.f, 0.f};
                const float4* encb = (const float4*)(enc + (size_t)b * Tq * Eq);
#pragma unroll 2
                for (int i = 0; i < 16; i++) {
                    int tt = (warp << 4) + i;
                    float wgt = sm.u.b.sc[tt];
                    float4 e0 = __ldg(encb + (size_t)tt * 64 + lane * 2);
                    float4 e1 = __ldg(encb + (size_t)tt * 64 + lane * 2 + 1);
                    a8[0] = fmaf(wgt, e0.x, a8[0]); a8[1] = fmaf(wgt, e0.y, a8[1]);
                    a8[2] = fmaf(wgt, e0.z, a8[2]); a8[3] = fmaf(wgt, e0.w, a8[3]);
                    a8[4] = fmaf(wgt, e1.x, a8[4]); a8[5] = fmaf(wgt, e1.y, a8[5]);
                    a8[6] = fmaf(wgt, e1.z, a8[6]); a8[7] = fmaf(wgt, e1.w, a8[7]);
                }
                __syncthreads();
#pragma unroll
                for (int j = 0; j < 8; j++) sm.u.b.ctxp[warp][lane * 8 + j] = a8[j];
                __syncthreads();
                float cv = 0.f;
#pragma unroll
                for (int w = 0; w < 8; w++) cv += sm.u.b.ctxp[w][tid];
                sm.u.b.ctx[tid] = cv * invs;
            }
            __syncthreads();

            // ============ epilogue needs gp ============
            wait_count(&g_cgp, tgt);

            // LSTM epilogue (thread = d)
            float yt = sm.u.b.misc[2];
            int d = tid;
            float gv[4];
#pragma unroll
            for (int g = 0; g < 4; g++) {
                float a = fmaf(yt, __ldg(&w_ih[g * 256 + d]), g_bsum[g * 256 + d]);
#pragma unroll
                for (int kq = 0; kq < 4; kq++)
                    a += __ldcg(&g_gp[(size_t)kq * (Bq * G4) + (size_t)b * G4 + g * 256 + d]);
                gv[g] = a;
            }
            float cprev = __ldcg(&g_c[b * Dq + d]);
            float cn = sigmoid_f(gv[1]) * cprev + sigmoid_f(gv[0]) * tanhf(gv[2]);
            float hn = sigmoid_f(gv[3]) * tanhf(cn);
            g_c[b * Dq + d] = cn;
            g_h[b * Dq + d] = hn;

            if (t == Tq - 1) {
                float q = hn * __ldg(&fcf_w[d]) + sm.u.b.ctx[d] * __ldg(&fcf_w[Dq + d]);
#pragma unroll
                for (int o = 16; o; o >>= 1) q += __shfl_xor_sync(0xffffffffu, q, o);
                __syncthreads();
                if (lane == 0) sm.u.b.red[warp] = q;
                __syncthreads();
                if (tid == 0) {
                    float tot = 0.f;
#pragma unroll
                    for (int w = 0; w < 8; w++) tot += sm.u.b.red[w];
                    out[b] = tot + fcf_b[0];
                }
            }
        }
        // ---- arrive: my h,c row is written ----
        post_count(my_ep_post);
    }
}

__global__ void prep_kernel(const float* __restrict__ w_hh,
                            const float* __restrict__ b_ih,
                            const float* __restrict__ b_hh)
{
    int i = blockIdx.x * blockDim.x + threadIdx.x;
    if (i < G4 * Dq) {
        int j = i >> 8, k = i & 255;
        g_whhT[(size_t)k * G4 + j] = w_hh[i];
    }
    if (i < G4) g_bsum[i] = b_ih[i] + b_hh[i];
    if (i < Bq * Dq) { g_h[i] = 0.f; g_c[i] = 0.f; }
    if (i < 4 * 32) g_cep[i] = 0u;
    if (i == 0) { g_chp = 0u; g_cgp = 0u; }
}

// encfc[b,t] = enc[b,t,:] . fc_w[0:256]   (one warp per (b,t))
__global__ void __launch_bounds__(256) encfc_kernel(
        const float* __restrict__ enc, const float* __restrict__ fc_w)
{
    int w = blockIdx.x * 8 + (threadIdx.x >> 5);
    int lane = threadIdx.x & 31;
    const float4* p = (const float4*)(enc + (size_t)w * Eq);
    const float4* q = (const float4*)fc_w;
    float s = 0.f;
#pragma unroll
    for (int j = 0; j < 2; j++) {
        float4 e = __ldcg(p + lane + 32 * j);
        float4 f = __ldg(q + lane + 32 * j);
        s += e.x * f.x + e.y * f.y + e.z * f.z + e.w * f.w;
    }
#pragma unroll
    for (int o = 16; o; o >>= 1) s += __shfl_xor_sync(0xffffffffu, s, o);
    if (lane == 0) g_encfc[w] = s;
}

__global__ void __launch_bounds__(256) pre_gemm_kernel(
        const float* __restrict__ enc, const float* __restrict__ attn_w1,
        const float* __restrict__ attn_b1)
{
    __shared__ SmA sa;
    int mt = blockIdx.x >> 2, nt = blockIdx.x & 3;
    gemm128x64<__half>(&sa,
        enc + (size_t)mt * 128 * Eq, Eq,
        attn_w1 + (size_t)(2 * Dq) * Eq + nt * 64, Eq,
        g_pre + (size_t)mt * 128 * Eq + nt * 64, Eq, 256,
        attn_b1 + nt * 64);
}

extern "C" void kernel_launch(void* const* d_in, const int* in_sizes, int n_in,
                              void* d_out, int out_size)
{
    const float* enc     = (const float*)d_in[0];
    const float* yhist   = (const float*)d_in[1];
    const float* attn_w1 = (const float*)d_in[2];
    const float* attn_b1 = (const float*)d_in[3];
    const float* attn_w2 = (const float*)d_in[4];
    // d_in[5] = attn_b2: unused (softmax is shift-invariant)
    const float* w_ih    = (const float*)d_in[6];
    const float* w_hh    = (const float*)d_in[7];
    const float* b_ih    = (const float*)d_in[8];
    const float* b_hh    = (const float*)d_in[9];
    const float* fc_w    = (const float*)d_in[10];
    const float* fc_b    = (const float*)d_in[11];
    const float* fcf_w   = (const float*)d_in[12];
    const float* fcf_b   = (const float*)d_in[13];
    float* out = (float*)d_out;

    prep_kernel<<<1024, 256>>>(w_hh, b_ih, b_hh);
    encfc_kernel<<<BT / 8, 256>>>(enc, fc_w);
    pre_gemm_kernel<<<2048, 256>>>(enc, attn_w1, attn_b1);
    decoder_persist<<<NBLK, 256>>>(enc, yhist, attn_w1, attn_w2, w_ih,
                                   fc_w, fc_b, fcf_w, fcf_b, out);
}

// round 17
// speedup vs baseline: 1.8838x; 1.0339x over previous
#include <cuda_runtime.h>
#include <cuda_fp16.h>

#define Bq 512
#define Tq 128
#define Eq 256
#define Dq 256
#define G4 1024
#define BT (Bq*Tq)
#define NBLK 512

// ---------------- static device scratch ----------------
__device__ __half g_pre[(size_t)BT * Eq];     // enc @ W1_enc + b1 (fp16, 32MB)
__device__ float g_encfc[BT];                 // enc[b,t,:] . fc_w[0:256]
__device__ float g_whhT[Dq * G4];             // w_hh transposed [k][gate*256+d]
__device__ float g_bsum[G4];
__device__ float g_h[Bq * Dq];
__device__ float g_c[Bq * Dq];
__device__ float g_hp[16 * Bq * Eq];          // 16 K-partials of [h|c]@W1_hc
__device__ float g_gp[4 * (size_t)Bq * G4];   // 4 K-partials of h@w_hhT
__device__ unsigned g_chp[4 * 32];            // per-row-group hp counters (128B apart)
__device__ unsigned g_cgp[4 * 32];            // per-row-group gp counters
__device__ unsigned g_cep[4 * 32];            // per-row-group epilogue counters

struct SmA { float As[16][136]; float Bs[16][68]; };   // prepass engine layout
struct SmStep { float As[16][132]; };                  // step engine: A slab only
struct SmB {
    float hp[256]; unsigned hp2[128]; float sc[128]; float ctxp[8][256];
    float ctx[256]; float red[8]; float misc[4];
};
struct SmAll {
    union { SmStep a; SmB b; SmA pp; } u;
    float Bper[64][68];                                // persistent B tile (<=16KB used)
};

__device__ __forceinline__ unsigned tanh_h2(unsigned x) {
    unsigned y; asm("tanh.approx.f16x2 %0, %1;" : "=r"(y) : "r"(x)); return y;
}
__device__ __forceinline__ float sigmoid_f(float x) {
    return __fdividef(1.0f, 1.0f + __expf(-x));
}

// packed dual-fp32 FMA
#define FMA_X2(acc, a, b) \
    asm("fma.rn.f32x2 %0, %1, %2, %0;" : "+l"(acc) : "l"(a), "l"(b))

__device__ __forceinline__ unsigned long long pack2(float lo, float hi) {
    unsigned long long r;
    asm("mov.b64 %0, {%1, %2};" : "=l"(r) : "f"(lo), "f"(hi));
    return r;
}
__device__ __forceinline__ float2 unpack2(unsigned long long v) {
    float lo, hi;
    asm("mov.b64 {%0, %1}, %2;" : "=f"(lo), "=f"(hi) : "l"(v));
    return make_float2(lo, hi);
}

// ---------------- step GEMM: A staged per slab, B persistent in smem ----------------
__device__ __forceinline__ void step_gemm(SmAll* sm,
        const float* __restrict__ A, int lda,
        float* __restrict__ C, int ldc, int K)
{
    const int tid = threadIdx.x;
    const int ty = tid >> 4, tx = tid & 15;
    const int arow = tid >> 2, ac4 = (tid & 3) << 2;

    unsigned long long acc2[4][4];
#pragma unroll
    for (int p = 0; p < 4; p++)
#pragma unroll
        for (int j = 0; j < 4; j++) acc2[p][j] = 0ull;

    for (int k0 = 0; k0 < K; k0 += 16) {
        float4 av0 = __ldcg((const float4*)(A + (size_t)arow * lda + k0 + ac4));
        float4 av1 = __ldcg((const float4*)(A + (size_t)(arow + 64) * lda + k0 + ac4));
        sm->u.a.As[ac4 + 0][arow] = av0.x; sm->u.a.As[ac4 + 1][arow] = av0.y;
        sm->u.a.As[ac4 + 2][arow] = av0.z; sm->u.a.As[ac4 + 3][arow] = av0.w;
        sm->u.a.As[ac4 + 0][arow + 64] = av1.x; sm->u.a.As[ac4 + 1][arow + 64] = av1.y;
        sm->u.a.As[ac4 + 2][arow + 64] = av1.z; sm->u.a.As[ac4 + 3][arow + 64] = av1.w;
        __syncthreads();
#pragma unroll
        for (int k = 0; k < 16; k++) {
            ulonglong2 aLo = *(const ulonglong2*)&sm->u.a.As[k][ty << 3];
            ulonglong2 aHi = *(const ulonglong2*)&sm->u.a.As[k][(ty << 3) + 4];
            float4 b4 = *(const float4*)&sm->Bper[k0 + k][tx << 2];
            unsigned long long bd0 = pack2(b4.x, b4.x);
            unsigned long long bd1 = pack2(b4.y, b4.y);
            unsigned long long bd2 = pack2(b4.z, b4.z);
            unsigned long long bd3 = pack2(b4.w, b4.w);
            FMA_X2(acc2[0][0], aLo.x, bd0); FMA_X2(acc2[0][1], aLo.x, bd1);
            FMA_X2(acc2[0][2], aLo.x, bd2); FMA_X2(acc2[0][3], aLo.x, bd3);
            FMA_X2(acc2[1][0], aLo.y, bd0); FMA_X2(acc2[1][1], aLo.y, bd1);
            FMA_X2(acc2[1][2], aLo.y, bd2); FMA_X2(acc2[1][3], aLo.y, bd3);
            FMA_X2(acc2[2][0], aHi.x, bd0); FMA_X2(acc2[2][1], aHi.x, bd1);
            FMA_X2(acc2[2][2], aHi.x, bd2); FMA_X2(acc2[2][3], aHi.x, bd3);
            FMA_X2(acc2[3][0], aHi.y, bd0); FMA_X2(acc2[3][1], aHi.y, bd1);
            FMA_X2(acc2[3][2], aHi.y, bd2); FMA_X2(acc2[3][3], aHi.y, bd3);
        }
        __syncthreads();
    }

#pragma unroll
    for (int p = 0; p < 4; p++) {
        float2 v0 = unpack2(acc2[p][0]);
        float2 v1 = unpack2(acc2[p][1]);
        float2 v2 = unpack2(acc2[p][2]);
        float2 v3 = unpack2(acc2[p][3]);
        size_t off0 = (size_t)((ty << 3) + 2 * p) * ldc + (tx << 2);
        size_t off1 = off0 + ldc;
        *(float4*)(C + off0) = make_float4(v0.x, v1.x, v2.x, v3.x);
        *(float4*)(C + off1) = make_float4(v0.y, v1.y, v2.y, v3.y);
    }
}

// ---------------- prepass GEMM (R11 engine, unchanged) ----------------
template<typename TO>
__device__ __forceinline__ void gemm128x64(SmA* s,
        const float* __restrict__ A, int lda,
        const float* __restrict__ Bm, int ldb,
        TO* __restrict__ C, int ldc, int K,
        const float* __restrict__ bias)
{
    const int tid = threadIdx.x;
    const int ty = tid >> 4, tx = tid & 15;
    const int arow = tid >> 2, ac4 = (tid & 3) << 2;
    const int bk = tid >> 4, bc4 = (tid & 15) << 2;

    unsigned long long acc2[4][4];
#pragma unroll
    for (int p = 0; p < 4; p++)
#pragma unroll
        for (int j = 0; j < 4; j++) acc2[p][j] = 0ull;

    for (int k0 = 0; k0 < K; k0 += 16) {
        float4 av0 = __ldcg((const float4*)(A + (size_t)arow * lda + k0 + ac4));
        float4 av1 = __ldcg((const float4*)(A + (size_t)(arow + 64) * lda + k0 + ac4));
        float4 bv  = __ldg((const float4*)(Bm + (size_t)(k0 + bk) * ldb + bc4));
        s->As[ac4 + 0][arow] = av0.x; s->As[ac4 + 1][arow] = av0.y;
        s->As[ac4 + 2][arow] = av0.z; s->As[ac4 + 3][arow] = av0.w;
        s->As[ac4 + 0][arow + 64] = av1.x; s->As[ac4 + 1][arow + 64] = av1.y;
        s->As[ac4 + 2][arow + 64] = av1.z; s->As[ac4 + 3][arow + 64] = av1.w;
        *(float4*)&s->Bs[bk][bc4] = bv;
        __syncthreads();
#pragma unroll
        for (int k = 0; k < 16; k++) {
            const float2* ap = (const float2*)&s->As[k][ty << 3];
            float4 b4 = *(const float4*)&s->Bs[k][tx << 2];
            unsigned long long bd0 = pack2(b4.x, b4.x);
            unsigned long long bd1 = pack2(b4.y, b4.y);
            unsigned long long bd2 = pack2(b4.z, b4.z);
            unsigned long long bd3 = pack2(b4.w, b4.w);
#pragma unroll
            for (int p = 0; p < 4; p++) {
                float2 a2 = ap[p];
                unsigned long long av = pack2(a2.x, a2.y);
                FMA_X2(acc2[p][0], av, bd0);
                FMA_X2(acc2[p][1], av, bd1);
                FMA_X2(acc2[p][2], av, bd2);
                FMA_X2(acc2[p][3], av, bd3);
            }
        }
        __syncthreads();
    }
#pragma unroll
    for (int p = 0; p < 4; p++) {
        float2 v0 = unpack2(acc2[p][0]);
        float2 v1 = unpack2(acc2[p][1]);
        float2 v2 = unpack2(acc2[p][2]);
        float2 v3 = unpack2(acc2[p][3]);
        float r0[4] = {v0.x, v1.x, v2.x, v3.x};
        float r1[4] = {v0.y, v1.y, v2.y, v3.y};
        if (bias) {
#pragma unroll
            for (int j = 0; j < 4; j++) {
                float bj = bias[(tx << 2) + j];
                r0[j] += bj; r1[j] += bj;
            }
        }
        size_t off0 = (size_t)((ty << 3) + 2 * p) * ldc + (tx << 2);
        size_t off1 = off0 + ldc;
        if constexpr (sizeof(TO) == 2) {
            __half2 h00 = __floats2half2_rn(r0[0], r0[1]);
            __half2 h01 = __floats2half2_rn(r0[2], r0[3]);
            __half2 h10 = __floats2half2_rn(r1[0], r1[1]);
            __half2 h11 = __floats2half2_rn(r1[2], r1[3]);
            uint2 u0; u0.x = *(unsigned*)&h00; u0.y = *(unsigned*)&h01;
            uint2 u1; u1.x = *(unsigned*)&h10; u1.y = *(unsigned*)&h11;
            *(uint2*)((__half*)C + off0) = u0;
            *(uint2*)((__half*)C + off1) = u1;
        } else {
            *(float4*)((float*)C + off0) = make_float4(r0[0], r0[1], r0[2], r0[3]);
            *(float4*)((float*)C + off1) = make_float4(r1[0], r1[1], r1[2], r1[3]);
        }
    }
    __syncthreads();
}

// ---- release: all stores visible, then one arrival per block ----
__device__ __forceinline__ void post_count(unsigned* c) {
    __threadfence();
    __syncthreads();
    if (threadIdx.x == 0) atomicAdd(c, 1u);
}
// ---- acquire: spin until target arrivals, then fence ----
__device__ __forceinline__ void wait_count(unsigned* c, unsigned target) {
    if (threadIdx.x == 0) {
        while (*(volatile unsigned*)c < target) __nanosleep(32);
    }
    __syncthreads();
    __threadfence();
}

__global__ void __launch_bounds__(256, 4) decoder_persist(
        const float* __restrict__ enc, const float* __restrict__ yhist,
        const float* __restrict__ attn_w1, const float* __restrict__ attn_w2,
        const float* __restrict__ w_ih,
        const float* __restrict__ fc_w, const float* __restrict__ fc_b,
        const float* __restrict__ fcf_w, const float* __restrict__ fcf_b,
        float* __restrict__ out)
{
    __shared__ SmAll sm;
    const int bid = blockIdx.x;
    const int tid = threadIdx.x;
    const int lane = tid & 31, warp = tid >> 5;
    const int b = bid;
    const bool is_gp = (bid < 256);
    const int bg = b >> 7;                      // my attention row group

    // ---- unit geometry + persistent B tile load (once) ----
    const float* Abase; int lda; float* Cbase; int ldc; int Kdim; int amt;
    {
        const float* Bm; int ldb; int Krows;
        if (is_gp) {
            int kq = bid & 3, tile = bid >> 2;
            int mt = tile >> 4, nt = tile & 15;
            amt = mt;
            Abase = g_h + (size_t)mt * 128 * Dq + kq * 64; lda = Dq;
            Bm = g_whhT + (size_t)(kq * 64) * G4 + nt * 64; ldb = G4; Krows = 64;
            Cbase = g_gp + (size_t)kq * (Bq * G4) + (size_t)mt * 128 * G4 + nt * 64;
            ldc = G4; Kdim = 64;
        } else {
            int u = bid - 256;
            int tile = u >> 4, kq = u & 15;
            int mt = tile >> 2, nt = tile & 3;
            amt = mt;
            Abase = (kq < 8 ? g_h + kq * 32 : g_c + (kq - 8) * 32)
                    + (size_t)mt * 128 * Dq; lda = Dq;
            Bm = attn_w1 + (size_t)(kq * 32) * Eq + nt * 64; ldb = Eq; Krows = 32;
            Cbase = g_hp + (size_t)kq * (Bq * Eq) + (size_t)mt * 128 * Eq + nt * 64;
            ldc = Eq; Kdim = 32;
        }
        for (int i = tid; i < Krows * 16; i += 256) {
            int kk = i >> 4, c4 = (i & 15) << 2;
            *(float4*)&sm.Bper[kk][c4] = __ldg((const float4*)(Bm + (size_t)kk * ldb + c4));
        }
        __syncthreads();
    }
    unsigned* my_ep_wait  = &g_cep[amt * 32];   // A rows' h,c producer group
    unsigned* my_ep_post  = &g_cep[bg * 32];
    unsigned* my_gemm_post = is_gp ? &g_cgp[amt * 32] : &g_chp[amt * 32];
    unsigned* my_hp_wait  = &g_chp[bg * 32];
    unsigned* my_gp_wait  = &g_cgp[bg * 32];

    for (int t = 0; t < Tq; t++) {
        const unsigned tgt = 64u * (unsigned)(t + 1);

        // ---- wait: my A-rows' h,c from step t-1 are written ----
        wait_count(my_ep_wait, 128u * (unsigned)t);

        // ============ phase 1: my GEMM partial, then per-group arrival ============
        step_gemm(&sm, Abase, lda, Cbase, ldc, Kdim);
        post_count(my_gemm_post);

        // ============ attention needs hp of my row group only ============
        wait_count(my_hp_wait, tgt);
        {
            float hpv = 0.f;
#pragma unroll
            for (int q = 0; q < 16; q++)
                hpv += __ldcg(&g_hp[(size_t)q * (Bq * Eq) + b * Eq + tid]);
            sm.u.b.hp[tid] = hpv;
            __syncthreads();
            if (tid < 128) {
                __half2 h2 = __floats2half2_rn(sm.u.b.hp[2 * tid], sm.u.b.hp[2 * tid + 1]);
                sm.u.b.hp2[tid] = *(unsigned*)&h2;
            }
            __syncthreads();

            unsigned hp2r[4];
            float w2r[8];
#pragma unroll
            for (int q = 0; q < 4; q++) hp2r[q] = sm.u.b.hp2[lane * 4 + q];
#pragma unroll
            for (int j = 0; j < 8; j++) w2r[j] = __ldg(&attn_w2[lane * 8 + j]);

            // scores: 8 warps x 16 t's, 4 loads in flight; tanh in f16x2
            const uint4* preb = (const uint4*)(g_pre + (size_t)b * Tq * Eq);
#pragma unroll
            for (int tb = 0; tb < 4; tb++) {
                int tt0 = warp + tb * 32;
                uint4 pv[4];
#pragma unroll
                for (int j = 0; j < 4; j++)
                    pv[j] = __ldg(preb + (size_t)(tt0 + j * 8) * 32 + lane);
#pragma unroll
                for (int j = 0; j < 4; j++) {
                    const unsigned* ph = (const unsigned*)&pv[j];
                    float a = 0.f;
#pragma unroll
                    for (int q = 0; q < 4; q++) {
                        __half2 x = *(const __half2*)&ph[q] + *(const __half2*)&hp2r[q];
                        unsigned th = tanh_h2(*(unsigned*)&x);
                        float2 f = __half22float2(*(const __half2*)&th);
                        a = fmaf(w2r[2 * q], f.x, a);
                        a = fmaf(w2r[2 * q + 1], f.y, a);
                    }
#pragma unroll
                    for (int o = 16; o; o >>= 1) a += __shfl_xor_sync(0xffffffffu, a, o);
                    if (lane == 0) sm.u.b.sc[tt0 + j * 8] = a;
                }
            }
            __syncthreads();

            // softmax over T=128 (attn_b2 dropped: shift-invariant)
            float sv = (tid < Tq) ? sm.u.b.sc[tid] : -3.0e38f;
            float m = sv;
#pragma unroll
            for (int o = 16; o; o >>= 1) m = fmaxf(m, __shfl_xor_sync(0xffffffffu, m, o));
            if (lane == 0) sm.u.b.red[warp] = m;
            __syncthreads();
            if (tid == 0) {
                float mm = sm.u.b.red[0];
#pragma unroll
                for (int w = 1; w < 8; w++) mm = fmaxf(mm, sm.u.b.red[w]);
                sm.u.b.misc[0] = mm;
            }
            __syncthreads();
            float ex = (tid < Tq) ? __expf(sv - sm.u.b.misc[0]) : 0.f;
            float ss = ex;
#pragma unroll
            for (int o = 16; o; o >>= 1) ss += __shfl_xor_sync(0xffffffffu, ss, o);
            if (lane == 0) sm.u.b.red[warp] = ss;
            __syncthreads();
            if (tid == 0) {
                float tot = 0.f;
#pragma unroll
                for (int w = 0; w < 8; w++) tot += sm.u.b.red[w];
                sm.u.b.misc[1] = __fdividef(1.0f, tot);
            }
            if (tid < Tq) sm.u.b.sc[tid] = ex;
            __syncthreads();
            float invs = sm.u.b.misc[1];

            // y_dot = sum_t ex[t] * encfc[b,t]
            float yd = (tid < Tq) ? sm.u.b.sc[tid] * __ldg(&g_encfc[b * Tq + tid]) : 0.f;
#pragma unroll
            for (int o = 16; o; o >>= 1) yd += __shfl_xor_sync(0xffffffffu, yd, o);
            if (lane == 0) sm.u.b.red[warp] = yd;
            __syncthreads();
            if (tid == 0) {
                float tot = 0.f;
#pragma unroll
                for (int w = 0; w < 8; w++) tot += sm.u.b.red[w];
                sm.u.b.misc[2] = tot * invs + __ldg(&yhist[b * Tq + t]) * fc_w[256] + fc_b[0];
            }

            // full ctx only at the final step (for fc_final)
            if (t == Tq - 1) {
                float a8[8] = {0.f, 0.f, 0.f, 0.f, 0.f, 0.f, 0.f, 0.f};
                const float4* encb = (const float4*)(enc + (size_t)b * Tq * Eq);
#pragma unroll 2
                for (int i = 0; i < 16; i++) {
                    int tt = (warp << 4) + i;
                    float wgt = sm.u.b.sc[tt];
                    float4 e0 = __ldg(encb + (size_t)tt * 64 + lane * 2);
                    float4 e1 = __ldg(encb + (size_t)tt * 64 + lane * 2 + 1);
                    a8[0] = fmaf(wgt, e0.x, a8[0]); a8[1] = fmaf(wgt, e0.y, a8[1]);
                    a8[2] = fmaf(wgt, e0.z, a8[2]); a8[3] = fmaf(wgt, e0.w, a8[3]);
                    a8[4] = fmaf(wgt, e1.x, a8[4]); a8[5] = fmaf(wgt, e1.y, a8[5]);
                    a8[6] = fmaf(wgt, e1.z, a8[6]); a8[7] = fmaf(wgt, e1.w, a8[7]);
                }
                __syncthreads();
#pragma unroll
                for (int j = 0; j < 8; j++) sm.u.b.ctxp[warp][lane * 8 + j] = a8[j];
                __syncthreads();
                float cv = 0.f;
#pragma unroll
                for (int w = 0; w < 8; w++) cv += sm.u.b.ctxp[w][tid];
                sm.u.b.ctx[tid] = cv * invs;
            }
            __syncthreads();

            // ============ epilogue needs gp of my row group only ============
            wait_count(my_gp_wait, tgt);

            // LSTM epilogue (thread = d)
            float yt = sm.u.b.misc[2];
            int d = tid;
            float gv[4];
#pragma unroll
            for (int g = 0; g < 4; g++) {
                float a = fmaf(yt, __ldg(&w_ih[g * 256 + d]), g_bsum[g * 256 + d]);
#pragma unroll
                for (int kq = 0; kq < 4; kq++)
                    a += __ldcg(&g_gp[(size_t)kq * (Bq * G4) + (size_t)b * G4 + g * 256 + d]);
                gv[g] = a;
            }
            float cprev = __ldcg(&g_c[b * Dq + d]);
            float cn = sigmoid_f(gv[1]) * cprev + sigmoid_f(gv[0]) * tanhf(gv[2]);
            float hn = sigmoid_f(gv[3]) * tanhf(cn);
            g_c[b * Dq + d] = cn;
            g_h[b * Dq + d] = hn;

            if (t == Tq - 1) {
                float q = hn * __ldg(&fcf_w[d]) + sm.u.b.ctx[d] * __ldg(&fcf_w[Dq + d]);
#pragma unroll
                for (int o = 16; o; o >>= 1) q += __shfl_xor_sync(0xffffffffu, q, o);
                __syncthreads();
                if (lane == 0) sm.u.b.red[warp] = q;
                __syncthreads();
                if (tid == 0) {
                    float tot = 0.f;
#pragma unroll
                    for (int w = 0; w < 8; w++) tot += sm.u.b.red[w];
                    out[b] = tot + fcf_b[0];
                }
            }
        }
        // ---- arrive: my h,c row is written ----
        post_count(my_ep_post);
    }
}

__global__ void prep_kernel(const float* __restrict__ w_hh,
                            const float* __restrict__ b_ih,
                            const float* __restrict__ b_hh)
{
    int i = blockIdx.x * blockDim.x + threadIdx.x;
    if (i < G4 * Dq) {
        int j = i >> 8, k = i & 255;
        g_whhT[(size_t)k * G4 + j] = w_hh[i];
    }
    if (i < G4) g_bsum[i] = b_ih[i] + b_hh[i];
    if (i < Bq * Dq) { g_h[i] = 0.f; g_c[i] = 0.f; }
    if (i < 4 * 32) { g_cep[i] = 0u; g_chp[i] = 0u; g_cgp[i] = 0u; }
}

// encfc[b,t] = enc[b,t,:] . fc_w[0:256]   (one warp per (b,t))
__global__ void __launch_bounds__(256) encfc_kernel(
        const float* __restrict__ enc, const float* __restrict__ fc_w)
{
    int w = blockIdx.x * 8 + (threadIdx.x >> 5);
    int lane = threadIdx.x & 31;
    const float4* p = (const float4*)(enc + (size_t)w * Eq);
    const float4* q = (const float4*)fc_w;
    float s = 0.f;
#pragma unroll
    for (int j = 0; j < 2; j++) {
        float4 e = __ldcg(p + lane + 32 * j);
        float4 f = __ldg(q + lane + 32 * j);
        s += e.x * f.x + e.y * f.y + e.z * f.z + e.w * f.w;
    }
#pragma unroll
    for (int o = 16; o; o >>= 1) s += __shfl_xor_sync(0xffffffffu, s, o);
    if (lane == 0) g_encfc[w] = s;
}

__global__ void __launch_bounds__(256) pre_gemm_kernel(
        const float* __restrict__ enc, const float* __restrict__ attn_w1,
        const float* __restrict__ attn_b1)
{
    __shared__ SmA sa;
    int mt = blockIdx.x >> 2, nt = blockIdx.x & 3;
    gemm128x64<__half>(&sa,
        enc + (size_t)mt * 128 * Eq, Eq,
        attn_w1 + (size_t)(2 * Dq) * Eq + nt * 64, Eq,
        g_pre + (size_t)mt * 128 * Eq + nt * 64, Eq, 256,
        attn_b1 + nt * 64);
}

extern "C" void kernel_launch(void* const* d_in, const int* in_sizes, int n_in,
                              void* d_out, int out_size)
{
    const float* enc     = (const float*)d_in[0];
    const float* yhist   = (const float*)d_in[1];
    const float* attn_w1 = (const float*)d_in[2];
    const float* attn_b1 = (const float*)d_in[3];
    const float* attn_w2 = (const float*)d_in[4];
    // d_in[5] = attn_b2: unused (softmax is shift-invariant)
    const float* w_ih    = (const float*)d_in[6];
    const float* w_hh    = (const float*)d_in[7];
    const float* b_ih    = (const float*)d_in[8];
    const float* b_hh    = (const float*)d_in[9];
    const float* fc_w    = (const float*)d_in[10];
    const float* fc_b    = (const float*)d_in[11];
    const float* fcf_w   = (const float*)d_in[12];
    const float* fcf_b   = (const float*)d_in[13];
    float* out = (float*)d_out;

    prep_kernel<<<1024, 256>>>(w_hh, b_ih, b_hh);
    encfc_kernel<<<BT / 8, 256>>>(enc, fc_w);
    pre_gemm_kernel<<<2048, 256>>>(enc, attn_w1, attn_b1);
    decoder_persist<<<NBLK, 256>>>(enc, yhist, attn_w1, attn_w2, w_ih,
                                   fc_w, fc_b, fcf_w, fcf_b, out);
}